// round 8
// baseline (speedup 1.0000x reference)
#include <cuda_runtime.h>
#include <cuda_bf16.h>
#include <math.h>
#include <stdint.h>

// ---------------- problem constants ----------------
#define BB   2
#define SS   4096
#define HIDN 2048
#define NH   16
#define HD   128
#define CC   256
#define NCC  16
#define MM   (BB*SS)          // 8192
#define QKVN (3*HIDN)         // 6144
#define GK   HIDN
#define BKC  64
#define NCHUNK (GK/BKC)       // 32

// ---------------- device scratch ----------------
__device__ float g_qkv   [(size_t)MM * QKVN];
__device__ float g_gate  [(size_t)MM * HIDN];
__device__ float g_kvdelta[(size_t)BB*NH*NCC*HD*HD];
__device__ float g_kvstate[(size_t)BB*NH*NCC*HD*HD];

__device__ __nv_bfloat16 g_xhi[(size_t)MM*HIDN],        g_xlo[(size_t)MM*HIDN];
__device__ __nv_bfloat16 g_wqkvT_hi[(size_t)QKVN*HIDN], g_wqkvT_lo[(size_t)QKVN*HIDN];
__device__ __nv_bfloat16 g_wgateT_hi[(size_t)HIDN*HIDN],g_wgateT_lo[(size_t)HIDN*HIDN];
__device__ __nv_bfloat16 g_woutT_hi[(size_t)HIDN*HIDN], g_woutT_lo[(size_t)HIDN*HIDN];
__device__ __nv_bfloat16 g_gahi[(size_t)MM*HIDN],       g_galo[(size_t)MM*HIDN];

#define PHSZ ((size_t)BB*NH*SS*HD)
__device__ __nv_bfloat16 g_q_hi [PHSZ], g_q_lo [PHSZ];    // [bh][s][d]
__device__ __nv_bfloat16 g_k_hi [PHSZ], g_k_lo [PHSZ];    // [bh][s][d]
__device__ __nv_bfloat16 g_kdT_hi[PHSZ], g_kdT_lo[PHSZ];  // [bh][d][s]
__device__ __nv_bfloat16 g_vT_hi [PHSZ], g_vT_lo [PHSZ];  // [bh][d][s]
__device__ __nv_bfloat16 g_kvsT_hi[(size_t)BB*NH*NCC*HD*HD], g_kvsT_lo[(size_t)BB*NH*NCC*HD*HD]; // [bhn][e][d']
__device__ float g_qdectab[NH*CC], g_kdectab[NH*CC];

// ---------------- epilogues ----------------
#define EPI_SILU    0
#define EPI_SIGMOID 1
#define EPI_NONE    2

__device__ __forceinline__ float apply_epi(float x, int mode) {
    if (mode == EPI_SILU)    return x / (1.0f + expf(-x));
    if (mode == EPI_SIGMOID) return 1.0f / (1.0f + expf(-x));
    return x;
}

// ---------------- base-ISA tensor-core helpers ----------------
__device__ __forceinline__ uint32_t smem_u32(const void* p) {
    uint32_t a;
    asm("{ .reg .u64 t; cvta.to.shared.u64 t, %1; cvt.u32.u64 %0, t; }" : "=r"(a) : "l"(p));
    return a;
}
__device__ __forceinline__ void cpasync16(uint32_t saddr, const void* g) {
    asm volatile("cp.async.cg.shared.global [%0], [%1], 16;" :: "r"(saddr), "l"(g));
}
__device__ __forceinline__ void cp_commit() {
    asm volatile("cp.async.commit_group;" ::: "memory");
}
template<int N> __device__ __forceinline__ void cp_wait() {
    asm volatile("cp.async.wait_group %0;" :: "n"(N) : "memory");
}
__device__ __forceinline__ void ldm_x4(uint32_t* r, uint32_t addr) {
    asm volatile("ldmatrix.sync.aligned.m8n8.x4.shared.b16 {%0,%1,%2,%3}, [%4];"
                 : "=r"(r[0]), "=r"(r[1]), "=r"(r[2]), "=r"(r[3]) : "r"(addr));
}
__device__ __forceinline__ void ldm_x2(uint32_t* r, uint32_t addr) {
    asm volatile("ldmatrix.sync.aligned.m8n8.x2.shared.b16 {%0,%1}, [%2];"
                 : "=r"(r[0]), "=r"(r[1]) : "r"(addr));
}
__device__ __forceinline__ void mma16816(float* c, const uint32_t* a, const uint32_t* b) {
    asm volatile(
        "mma.sync.aligned.m16n8k16.row.col.f32.bf16.bf16.f32 "
        "{%0,%1,%2,%3},{%4,%5,%6,%7},{%8,%9},{%0,%1,%2,%3};"
        : "+f"(c[0]), "+f"(c[1]), "+f"(c[2]), "+f"(c[3])
        : "r"(a[0]), "r"(a[1]), "r"(a[2]), "r"(a[3]), "r"(b[0]), "r"(b[1]));
}

// ---------------- HMMA split-bf16 GEMM: 128(M)x256(N) tile, 512 threads ----------------
// smem per buffer: Ahi(128x144) Alo(128x144) Bhi(256x144) Blo(256x144)
#define LDSW   144
#define GA_SZ  (128 * LDSW)               // 18432
#define GB_SZ  (256 * LDSW)               // 36864
#define GBUF   (2 * GA_SZ + 2 * GB_SZ)    // 110592
#define GEMM_SMEM (2 * GBUF)              // 221184

template<int EPI>
__global__ __launch_bounds__(512) void mma_gemm(
    const __nv_bfloat16* __restrict__ Ahi, const __nv_bfloat16* __restrict__ Alo,
    const __nv_bfloat16* __restrict__ Bhi, const __nv_bfloat16* __restrict__ Blo,
    float* __restrict__ C, int M, int N)
{
    extern __shared__ char smraw[];
    const uint32_t sb = smem_u32(smraw);

    const int tid  = threadIdx.x;
    const int lane = tid & 31;
    const int wid  = tid >> 5;            // 0..15
    const int bm = blockIdx.y * 128;
    const int bn = blockIdx.x * 256;
    const int wm = (wid >> 3) * 64;       // 0 / 64
    const int wn = (wid & 7) * 32;        // 0..224

    auto prefetch = [&](int c, int buf) {
        const uint32_t bbase = sb + buf * GBUF;
        const int k0 = c * BKC;
        // A: 128 rows x 8 sectors = 1024, 2 per thread
        #pragma unroll
        for (int i = 0; i < 2; ++i) {
            int idx = tid + 512 * i;
            int row = idx >> 3, sec = idx & 7;
            const uint32_t so = row * LDSW + sec * 16;
            const size_t ga = (size_t)(bm + row) * GK + k0 + sec * 8;
            cpasync16(bbase + 0 * GA_SZ + so, Ahi + ga);
            cpasync16(bbase + 1 * GA_SZ + so, Alo + ga);
        }
        // B: 256 rows x 8 sectors = 2048, 4 per thread
        #pragma unroll
        for (int i = 0; i < 4; ++i) {
            int idx = tid + 512 * i;
            int row = idx >> 3, sec = idx & 7;
            const uint32_t so = row * LDSW + sec * 16;
            const size_t gb = (size_t)(bn + row) * GK + k0 + sec * 8;
            cpasync16(bbase + 2 * GA_SZ + so, Bhi + gb);
            cpasync16(bbase + 2 * GA_SZ + GB_SZ + so, Blo + gb);
        }
        cp_commit();
    };

    float acc[4][4][4];
    #pragma unroll
    for (int mi = 0; mi < 4; ++mi)
        #pragma unroll
        for (int ni = 0; ni < 4; ++ni)
            #pragma unroll
            for (int r = 0; r < 4; ++r) acc[mi][ni][r] = 0.0f;

    const uint32_t aOff = (uint32_t)(wm + (lane & 15)) * LDSW + (lane >> 4) * 16;
    const uint32_t bOff = (uint32_t)(wn + (lane & 7))  * LDSW + ((lane >> 3) & 1) * 16;

    prefetch(0, 0);

    for (int c = 0; c < NCHUNK; ++c) {
        const int cur = c & 1;
        if (c + 1 < NCHUNK) prefetch(c + 1, cur ^ 1);
        if (c + 1 < NCHUNK) cp_wait<1>(); else cp_wait<0>();
        __syncthreads();

        const uint32_t bbase = sb + cur * GBUF;
        #pragma unroll
        for (int ks = 0; ks < 4; ++ks) {
            const uint32_t kso = ks * 32;
            uint32_t aH[4][4], aL[4][4], bH[4][2], bL[4][2];
            #pragma unroll
            for (int mi = 0; mi < 4; ++mi) {
                ldm_x4(aH[mi], bbase + 0 * GA_SZ + aOff + mi * 16 * LDSW + kso);
                ldm_x4(aL[mi], bbase + 1 * GA_SZ + aOff + mi * 16 * LDSW + kso);
            }
            #pragma unroll
            for (int ni = 0; ni < 4; ++ni) {
                ldm_x2(bH[ni], bbase + 2 * GA_SZ + bOff + ni * 8 * LDSW + kso);
                ldm_x2(bL[ni], bbase + 2 * GA_SZ + GB_SZ + bOff + ni * 8 * LDSW + kso);
            }
            #pragma unroll
            for (int mi = 0; mi < 4; ++mi)
                #pragma unroll
                for (int ni = 0; ni < 4; ++ni)
                    mma16816(acc[mi][ni], aH[mi], bH[ni]);
            #pragma unroll
            for (int mi = 0; mi < 4; ++mi)
                #pragma unroll
                for (int ni = 0; ni < 4; ++ni)
                    mma16816(acc[mi][ni], aH[mi], bL[ni]);
            #pragma unroll
            for (int mi = 0; mi < 4; ++mi)
                #pragma unroll
                for (int ni = 0; ni < 4; ++ni)
                    mma16816(acc[mi][ni], aL[mi], bH[ni]);
        }
        __syncthreads();
    }

    const int erow = lane >> 2;
    const int ecol = 2 * (lane & 3);
    #pragma unroll
    for (int mi = 0; mi < 4; ++mi) {
        #pragma unroll
        for (int ni = 0; ni < 4; ++ni) {
            const int gr0 = bm + wm + mi * 16 + erow;
            const int gc  = bn + wn + ni * 8 + ecol;
            float2 v0, v1;
            v0.x = apply_epi(acc[mi][ni][0], EPI);
            v0.y = apply_epi(acc[mi][ni][1], EPI);
            v1.x = apply_epi(acc[mi][ni][2], EPI);
            v1.y = apply_epi(acc[mi][ni][3], EPI);
            *(float2*)(C + (size_t)gr0 * N + gc)       = v0;
            *(float2*)(C + (size_t)(gr0 + 8) * N + gc) = v1;
        }
    }
}

// ---------------- conversion kernels ----------------
__device__ __forceinline__ void split_store4(
    __nv_bfloat16* hi, __nv_bfloat16* lo, size_t o, float4 v, float scale)
{
    float a[4] = {v.x * scale, v.y * scale, v.z * scale, v.w * scale};
    __nv_bfloat16 h[4], l[4];
    #pragma unroll
    for (int j = 0; j < 4; j++) {
        h[j] = __float2bfloat16(a[j]);
        l[j] = __float2bfloat16(a[j] - __bfloat162float(h[j]));
    }
    *(__nv_bfloat162*)(hi + o)     = __halves2bfloat162(h[0], h[1]);
    *(__nv_bfloat162*)(hi + o + 2) = __halves2bfloat162(h[2], h[3]);
    *(__nv_bfloat162*)(lo + o)     = __halves2bfloat162(l[0], l[1]);
    *(__nv_bfloat162*)(lo + o + 2) = __halves2bfloat162(l[2], l[3]);
}

__global__ __launch_bounds__(256) void split_kernel(
    const float* __restrict__ in, __nv_bfloat16* __restrict__ hi,
    __nv_bfloat16* __restrict__ lo, int n4)
{
    int i = blockIdx.x * 256 + threadIdx.x;
    if (i >= n4) return;
    split_store4(hi, lo, (size_t)i * 4, ((const float4*)in)[i], 1.0f);
}

__global__ __launch_bounds__(256) void transp_split_kernel(
    const float* __restrict__ w, __nv_bfloat16* __restrict__ thi,
    __nv_bfloat16* __restrict__ tlo, int K, int N)
{
    __shared__ float t[32][33];
    const int n0 = blockIdx.x * 32, k0 = blockIdx.y * 32;
    const int x = threadIdx.x, y = threadIdx.y;
    #pragma unroll
    for (int r = 0; r < 32; r += 8)
        t[y + r][x] = w[(size_t)(k0 + y + r) * N + n0 + x];
    __syncthreads();
    #pragma unroll
    for (int r = 0; r < 32; r += 8) {
        float v = t[x][y + r];
        __nv_bfloat16 h = __float2bfloat16(v);
        __nv_bfloat16 l = __float2bfloat16(v - __bfloat162float(h));
        size_t o = (size_t)(n0 + y + r) * K + k0 + x;
        thi[o] = h;
        tlo[o] = l;
    }
}

__global__ void dectab_kernel(const float* __restrict__ slopes)
{
    int h = blockIdx.x, i = threadIdx.x;
    float s = slopes[h];
    g_qdectab[h * CC + i] = expf(-s * (float)(i + 1));
    g_kdectab[h * CC + i] = expf(-s * (float)(CC - 1 - i));
}

// g_qkv -> q, k in [bh][s][d] bf16 split
__global__ __launch_bounds__(256) void splitqkv_norm()
{
    int idx = blockIdx.x * 256 + threadIdx.x;
    int d4 = idx & 31; int rest = idx >> 5;
    int h = rest & 15; rest >>= 4;
    int s = rest & 4095; int b = rest >> 12;

    size_t qo = (size_t)(b * SS + s) * QKVN + h * HD + d4 * 4;
    float4 q = *(const float4*)&g_qkv[qo];
    float4 k = *(const float4*)&g_qkv[qo + HIDN];

    size_t o = ((size_t)(b * NH + h) * SS + s) * HD + d4 * 4;
    split_store4(g_q_hi, g_q_lo, o, q, 1.0f);
    split_store4(g_k_hi, g_k_lo, o, k, 1.0f);
}

// g_qkv k,v -> kdT, vT in [bh][d][s] bf16 split
__global__ void trans_split_head()
{
    __shared__ float tk[32][33], tv[32][33];
    const int z  = blockIdx.z;
    const int b  = z >> 4, h = z & 15;
    const int s0 = blockIdx.x * 32;
    const int d0 = blockIdx.y * 32;
    const int x = threadIdx.x, y = threadIdx.y;

    #pragma unroll
    for (int r = 0; r < 32; r += 8) {
        size_t base = (size_t)(b * SS + s0 + y + r) * QKVN + h * HD + d0 + x;
        tk[y + r][x] = g_qkv[base + HIDN];
        tv[y + r][x] = g_qkv[base + 2 * HIDN];
    }
    __syncthreads();
    #pragma unroll
    for (int r = 0; r < 32; r += 8) {
        int d = d0 + y + r;
        int s = s0 + x;
        float kdec = g_kdectab[h * CC + (s & (CC - 1))];
        float kv = tk[x][y + r] * kdec;
        float vv = tv[x][y + r];
        size_t o = ((size_t)z * HD + d) * SS + s;
        __nv_bfloat16 h1 = __float2bfloat16(kv);
        g_kdT_hi[o] = h1;
        g_kdT_lo[o] = __float2bfloat16(kv - __bfloat162float(h1));
        __nv_bfloat16 h2 = __float2bfloat16(vv);
        g_vT_hi[o] = h2;
        g_vT_lo[o] = __float2bfloat16(vv - __bfloat162float(h2));
    }
}

// g_kvstate [bhn][d'][e] -> kvsT [bhn][e][d'] bf16 split
__global__ void kvsplitT_kernel()
{
    __shared__ float t[32][33];
    const int bhn = blockIdx.z;
    const int d0 = blockIdx.x * 32;
    const int e0 = blockIdx.y * 32;
    const int x = threadIdx.x, y = threadIdx.y;
    const size_t base = (size_t)bhn * HD * HD;

    #pragma unroll
    for (int r = 0; r < 32; r += 8)
        t[y + r][x] = g_kvstate[base + (size_t)(d0 + y + r) * HD + e0 + x];
    __syncthreads();
    #pragma unroll
    for (int r = 0; r < 32; r += 8) {
        float v = t[x][y + r];
        size_t o = base + (size_t)(e0 + y + r) * HD + d0 + x;
        __nv_bfloat16 h1 = __float2bfloat16(v);
        g_kvsT_hi[o] = h1;
        g_kvsT_lo[o] = __float2bfloat16(v - __bfloat162float(h1));
    }
}

// ---------------- kvdelta via HMMA (double-buffered) ----------------
#define KD_MAT  18432
#define KD_BUF  (4 * KD_MAT)          // 73728
#define KD_SMEM (2 * KD_BUF)          // 147456

__global__ __launch_bounds__(256) void kvdelta_mma()
{
    extern __shared__ char smraw[];
    const uint32_t sb = smem_u32(smraw);

    const int blk = blockIdx.x;
    const int n  = blk & (NCC - 1);
    const int bh = blk >> 4;
    const size_t colb = (size_t)bh * HD;

    const int tid = threadIdx.x, lane = tid & 31, wid = tid >> 5;
    const int wm = (wid >> 2) * 64;
    const int wn = (wid & 3) * 32;

    auto prefetch = [&](int kt, int buf) {
        const uint32_t bbase = sb + buf * KD_BUF;
        const int k0 = n * CC + kt * 64;
        #pragma unroll
        for (int it = 0; it < 4; ++it) {
            int idx = tid + 256 * it;
            int row = idx >> 3, sec = idx & 7;
            size_t g = (colb + row) * SS + k0 + sec * 8;
            uint32_t so = row * 144 + sec * 16;
            cpasync16(bbase + 0 * KD_MAT + so, g_kdT_hi + g);
            cpasync16(bbase + 1 * KD_MAT + so, g_kdT_lo + g);
            cpasync16(bbase + 2 * KD_MAT + so, g_vT_hi + g);
            cpasync16(bbase + 3 * KD_MAT + so, g_vT_lo + g);
        }
        cp_commit();
    };

    float acc[4][4][4];
    #pragma unroll
    for (int mi = 0; mi < 4; ++mi)
        #pragma unroll
        for (int ni = 0; ni < 4; ++ni)
            #pragma unroll
            for (int r = 0; r < 4; ++r) acc[mi][ni][r] = 0.0f;

    prefetch(0, 0);

    for (int kt = 0; kt < 4; ++kt) {
        const int cur = kt & 1;
        if (kt + 1 < 4) prefetch(kt + 1, cur ^ 1);
        if (kt + 1 < 4) cp_wait<1>(); else cp_wait<0>();
        __syncthreads();

        const uint32_t bbase = sb + cur * KD_BUF;
        #pragma unroll
        for (int ks = 0; ks < 4; ++ks) {
            uint32_t aH[4][4], aL[4][4], bH[4][2], bL[4][2];
            const uint32_t ao = (uint32_t)(lane & 15) * 144 + (lane >> 4) * 16 + ks * 32;
            #pragma unroll
            for (int mi = 0; mi < 4; ++mi) {
                ldm_x4(aH[mi], bbase + 0 * KD_MAT + (wm + mi * 16) * 144 + ao);
                ldm_x4(aL[mi], bbase + 1 * KD_MAT + (wm + mi * 16) * 144 + ao);
            }
            const uint32_t bo = (uint32_t)(lane & 7) * 144 + ((lane >> 3) & 1) * 16 + ks * 32;
            #pragma unroll
            for (int ni = 0; ni < 4; ++ni) {
                ldm_x2(bH[ni], bbase + 2 * KD_MAT + (wn + ni * 8) * 144 + bo);
                ldm_x2(bL[ni], bbase + 3 * KD_MAT + (wn + ni * 8) * 144 + bo);
            }
            #pragma unroll
            for (int mi = 0; mi < 4; ++mi)
                #pragma unroll
                for (int ni = 0; ni < 4; ++ni)
                    mma16816(acc[mi][ni], aH[mi], bH[ni]);
            #pragma unroll
            for (int mi = 0; mi < 4; ++mi)
                #pragma unroll
                for (int ni = 0; ni < 4; ++ni)
                    mma16816(acc[mi][ni], aH[mi], bL[ni]);
            #pragma unroll
            for (int mi = 0; mi < 4; ++mi)
                #pragma unroll
                for (int ni = 0; ni < 4; ++ni)
                    mma16816(acc[mi][ni], aL[mi], bH[ni]);
        }
        __syncthreads();
    }

    const int erow = lane >> 2, ecol = 2 * (lane & 3);
    float* out = &g_kvdelta[(size_t)blk * HD * HD];
    #pragma unroll
    for (int mi = 0; mi < 4; ++mi) {
        #pragma unroll
        for (int ni = 0; ni < 4; ++ni) {
            int d = wm + mi * 16 + erow;
            int e = wn + ni * 8 + ecol;
            *(float2*)(out + (size_t)d * HD + e)       = make_float2(acc[mi][ni][0], acc[mi][ni][1]);
            *(float2*)(out + (size_t)(d + 8) * HD + e) = make_float2(acc[mi][ni][2], acc[mi][ni][3]);
        }
    }
}

// ---------------- scan (parallel) ----------------
__global__ __launch_bounds__(256) void scan_kernel(const float* __restrict__ slopes)
{
    const int gid = blockIdx.x * 256 + threadIdx.x;
    const int bh  = gid >> 14;
    const int p   = gid & 16383;
    const float bd = expf(-slopes[bh & (NH - 1)] * (float)CC);
    const size_t base = (size_t)bh * NCC * HD * HD + p;

    float st = 0.0f;
    #pragma unroll
    for (int nn = 0; nn < NCC; nn++) {
        g_kvstate[base + (size_t)nn * HD * HD] = st;
        st = bd * st + g_kvdelta[base + (size_t)nn * HD * HD];
    }
}

// ---------------- fused attention via HMMA (pipelined, inter-first) ----------------
#define A_QHI   0
#define A_QLO   34816
#define A_KHI   69632
#define A_KLO   87040
#define A_VT0   104448
#define A_VT1   141312
#define A_SHI   178176
#define A_SLO   196608
#define A_SMEM  215040
#define A_KVSHI 69632
#define A_KVSLO 178176

__global__ __launch_bounds__(256) void attn_mma(const float* __restrict__ slopes)
{
    extern __shared__ char smraw[];
    const uint32_t sb = smem_u32(smraw);
    __shared__ float sdec[CC];

    const int blk = blockIdx.x;
    const int itile = blockIdx.y;
    const int n  = blk & (NCC - 1);
    const int bh = blk >> 4;
    const int h  = bh & (NH - 1);
    const int b  = bh >> 4;
    const float s = slopes[h];

    const int tid = threadIdx.x, lane = tid & 31, wid = tid >> 5;
    sdec[tid] = expf(-s * (float)tid);
    const float fexp = expf(-s);

    const size_t rowb = (size_t)bh * SS + n * CC;
    const size_t colb = (size_t)bh * HD;
    const int i0 = itile * 128;

    // group 0: q tile + kvsT (inter operand)
    #pragma unroll
    for (int it = 0; it < 8; ++it) {
        int idx = tid + 256 * it;
        int row = idx >> 4, sec = idx & 15;
        size_t g = (rowb + i0 + row) * HD + sec * 8;
        uint32_t so = row * 272 + sec * 16;
        cpasync16(sb + A_QHI + so, g_q_hi + g);
        cpasync16(sb + A_QLO + so, g_q_lo + g);
    }
    {
        const size_t kvb = (size_t)blk * HD * HD;
        #pragma unroll
        for (int it = 0; it < 8; ++it) {
            int idx = tid + 256 * it;
            int row = idx >> 4, sec = idx & 15;
            size_t g = kvb + (size_t)row * HD + sec * 8;
            uint32_t so = row * 272 + sec * 16;
            cpasync16(sb + A_KVSHI + so, g_kvsT_hi + g);
            cpasync16(sb + A_KVSLO + so, g_kvsT_lo + g);
        }
    }
    cp_commit();

    // group 1: vT(j=0) into buf0
    #pragma unroll
    for (int it = 0; it < 4; ++it) {
        int idx = tid + 256 * it;
        int row = idx >> 3, sec = idx & 7;
        size_t g = (colb + row) * SS + n * CC + sec * 8;
        uint32_t so = row * 144 + sec * 16;
        cpasync16(sb + A_VT0 + so, g_vT_hi + g);
        cpasync16(sb + A_VT0 + 18432 + so, g_vT_lo + g);
    }
    cp_commit();

    const int wm  = (wid >> 2) * 64;
    const int wns = (wid & 3) * 16;
    const int wno = (wid & 3) * 32;
    const int erow = lane >> 2, ecol = 2 * (lane & 3);

    float oacc[4][4][4];
    #pragma unroll
    for (int mi = 0; mi < 4; ++mi)
        #pragma unroll
        for (int ni = 0; ni < 4; ++ni)
            #pragma unroll
            for (int r = 0; r < 4; ++r) oacc[mi][ni][r] = 0.0f;

    // ---- inter FIRST: oacc = q @ kvsT, then row-scale by qdec ----
    cp_wait<1>();
    __syncthreads();

    #pragma unroll
    for (int ks = 0; ks < 8; ++ks) {
        uint32_t aH[4][4], aL[4][4], bH[4][2], bL[4][2];
        const uint32_t ao = (uint32_t)(lane & 15) * 272 + (lane >> 4) * 16 + ks * 32;
        #pragma unroll
        for (int mi = 0; mi < 4; ++mi) {
            ldm_x4(aH[mi], sb + A_QHI + (wm + mi * 16) * 272 + ao);
            ldm_x4(aL[mi], sb + A_QLO + (wm + mi * 16) * 272 + ao);
        }
        const uint32_t bo = (uint32_t)(lane & 7) * 272 + ((lane >> 3) & 1) * 16 + ks * 32;
        #pragma unroll
        for (int ni = 0; ni < 4; ++ni) {
            ldm_x2(bH[ni], sb + A_KVSHI + (wno + ni * 8) * 272 + bo);
            ldm_x2(bL[ni], sb + A_KVSLO + (wno + ni * 8) * 272 + bo);
        }
        #pragma unroll
        for (int mi = 0; mi < 4; ++mi)
            #pragma unroll
            for (int ni = 0; ni < 4; ++ni)
                mma16816(oacc[mi][ni], aH[mi], bH[ni]);
        #pragma unroll
        for (int mi = 0; mi < 4; ++mi)
            #pragma unroll
            for (int ni = 0; ni < 4; ++ni)
                mma16816(oacc[mi][ni], aH[mi], bL[ni]);
        #pragma unroll
        for (int mi = 0; mi < 4; ++mi)
            #pragma unroll
            for (int ni = 0; ni < 4; ++ni)
                mma16816(oacc[mi][ni], aL[mi], bH[ni]);
    }
    #pragma unroll
    for (int mi = 0; mi < 4; ++mi) {
        const int il0 = wm + mi * 16 + erow;
        const float qd0 = sdec[i0 + il0] * fexp;
        const float qd1 = sdec[i0 + il0 + 8] * fexp;
        #pragma unroll
        for (int ni = 0; ni < 4; ++ni) {
            oacc[mi][ni][0] *= qd0;
            oacc[mi][ni][1] *= qd0;
            oacc[mi][ni][2] *= qd1;
            oacc[mi][ni][3] *= qd1;
        }
    }
    __syncthreads();

    // load k(0)
    #pragma unroll
    for (int it = 0; it < 4; ++it) {
        int idx = tid + 256 * it;
        int row = idx >> 4, sec = idx & 15;
        size_t g = (rowb + row) * HD + sec * 8;
        uint32_t so = row * 272 + sec * 16;
        cpasync16(sb + A_KHI + so, g_k_hi + g);
        cpasync16(sb + A_KLO + so, g_k_lo + g);
    }
    cp_commit();

    const int njt = 2 * (itile + 1);
    for (int jt = 0; jt < njt; ++jt) {
        const int j0 = jt * 64;
        const int cur = jt & 1;
        const uint32_t vtb = sb + (cur ? A_VT1 : A_VT0);

        cp_wait<0>();
        __syncthreads();

        // ---- S = q @ k^T ----
        float sacc[4][2][4];
        #pragma unroll
        for (int mi = 0; mi < 4; ++mi)
            #pragma unroll
            for (int ni = 0; ni < 2; ++ni)
                #pragma unroll
                for (int r = 0; r < 4; ++r) sacc[mi][ni][r] = 0.0f;

        #pragma unroll
        for (int ks = 0; ks < 8; ++ks) {
            uint32_t aH[4][4], aL[4][4], bH[2][2], bL[2][2];
            const uint32_t ao = (uint32_t)(lane & 15) * 272 + (lane >> 4) * 16 + ks * 32;
            #pragma unroll
            for (int mi = 0; mi < 4; ++mi) {
                ldm_x4(aH[mi], sb + A_QHI + (wm + mi * 16) * 272 + ao);
                ldm_x4(aL[mi], sb + A_QLO + (wm + mi * 16) * 272 + ao);
            }
            const uint32_t bo = (uint32_t)(lane & 7) * 272 + ((lane >> 3) & 1) * 16 + ks * 32;
            #pragma unroll
            for (int ni = 0; ni < 2; ++ni) {
                ldm_x2(bH[ni], sb + A_KHI + (wns + ni * 8) * 272 + bo);
                ldm_x2(bL[ni], sb + A_KLO + (wns + ni * 8) * 272 + bo);
            }
            #pragma unroll
            for (int mi = 0; mi < 4; ++mi)
                #pragma unroll
                for (int ni = 0; ni < 2; ++ni)
                    mma16816(sacc[mi][ni], aH[mi], bH[ni]);
            #pragma unroll
            for (int mi = 0; mi < 4; ++mi)
                #pragma unroll
                for (int ni = 0; ni < 2; ++ni)
                    mma16816(sacc[mi][ni], aH[mi], bL[ni]);
            #pragma unroll
            for (int mi = 0; mi < 4; ++mi)
                #pragma unroll
                for (int ni = 0; ni < 2; ++ni)
                    mma16816(sacc[mi][ni], aL[mi], bH[ni]);
        }

        // ---- decay + split S ----
        #pragma unroll
        for (int mi = 0; mi < 4; ++mi) {
            #pragma unroll
            for (int ni = 0; ni < 2; ++ni) {
                #pragma unroll
                for (int r = 0; r < 4; ++r) {
                    int il = wm + mi * 16 + erow + (r >> 1) * 8;
                    int jl = wns + ni * 8 + ecol + (r & 1);
                    int dd = (i0 + il) - (j0 + jl);
                    float val = (dd >= 0) ? sacc[mi][ni][r] * sdec[dd] : 0.0f;
                    __nv_bfloat16 hi = __float2bfloat16(val);
                    __nv_bfloat16 lo = __float2bfloat16(val - __bfloat162float(hi));
                    *(__nv_bfloat16*)(smraw + A_SHI + il * 144 + jl * 2) = hi;
                    *(__nv_bfloat16*)(smraw + A_SLO + il * 144 + jl * 2) = lo;
                }
            }
        }
        __syncthreads();

        // prefetch k(jt+1) and vT(jt+1)
        if (jt + 1 < njt) {
            const int jn = (jt + 1) * 64;
            #pragma unroll
            for (int it = 0; it < 4; ++it) {
                int idx = tid + 256 * it;
                int row = idx >> 4, sec = idx & 15;
                size_t g = (rowb + jn + row) * HD + sec * 8;
                uint32_t so = row * 272 + sec * 16;
                cpasync16(sb + A_KHI + so, g_k_hi + g);
                cpasync16(sb + A_KLO + so, g_k_lo + g);
            }
            const uint32_t vtn = sb + (cur ? A_VT0 : A_VT1);
            #pragma unroll
            for (int it = 0; it < 4; ++it) {
                int idx = tid + 256 * it;
                int row = idx >> 3, sec = idx & 7;
                size_t g = (colb + row) * SS + n * CC + jn + sec * 8;
                uint32_t so = row * 144 + sec * 16;
                cpasync16(vtn + so, g_vT_hi + g);
                cpasync16(vtn + 18432 + so, g_vT_lo + g);
            }
            cp_commit();
        }

        // ---- O += S̃ @ v ----
        #pragma unroll
        for (int ks = 0; ks < 4; ++ks) {
            uint32_t aH[4][4], aL[4][4], bH[4][2], bL[4][2];
            const uint32_t ao = (uint32_t)(lane & 15) * 144 + (lane >> 4) * 16 + ks * 32;
            #pragma unroll
            for (int mi = 0; mi < 4; ++mi) {
                ldm_x4(aH[mi], sb + A_SHI + (wm + mi * 16) * 144 + ao);
                ldm_x4(aL[mi], sb + A_SLO + (wm + mi * 16) * 144 + ao);
            }
            const uint32_t bo = (uint32_t)(lane & 7) * 144 + ((lane >> 3) & 1) * 16 + ks * 32;
            #pragma unroll
            for (int ni = 0; ni < 4; ++ni) {
                ldm_x2(bH[ni], vtb + (wno + ni * 8) * 144 + bo);
                ldm_x2(bL[ni], vtb + 18432 + (wno + ni * 8) * 144 + bo);
            }
            #pragma unroll
            for (int mi = 0; mi < 4; ++mi)
                #pragma unroll
                for (int ni = 0; ni < 4; ++ni)
                    mma16816(oacc[mi][ni], aH[mi], bH[ni]);
            #pragma unroll
            for (int mi = 0; mi < 4; ++mi)
                #pragma unroll
                for (int ni = 0; ni < 4; ++ni)
                    mma16816(oacc[mi][ni], aH[mi], bL[ni]);
            #pragma unroll
            for (int mi = 0; mi < 4; ++mi)
                #pragma unroll
                for (int ni = 0; ni < 4; ++ni)
                    mma16816(oacc[mi][ni], aL[mi], bH[ni]);
        }
    }

    // ---- epilogue: gate-fused split store ----
    #pragma unroll
    for (int mi = 0; mi < 4; ++mi) {
        #pragma unroll
        for (int ni = 0; ni < 4; ++ni) {
            int il = wm + mi * 16 + erow;
            int e  = wno + ni * 8 + ecol;
            size_t o0 = (size_t)(b * SS + n * CC + i0 + il) * HIDN + h * HD + e;
            size_t o1 = o0 + 8 * HIDN;
            float2 g0 = *(const float2*)(g_gate + o0);
            float2 g1 = *(const float2*)(g_gate + o1);
            float v0 = oacc[mi][ni][0] * g0.x;
            float v1 = oacc[mi][ni][1] * g0.y;
            float v2 = oacc[mi][ni][2] * g1.x;
            float v3 = oacc[mi][ni][3] * g1.y;
            __nv_bfloat16 h0 = __float2bfloat16(v0), h1b = __float2bfloat16(v1);
            __nv_bfloat16 h2 = __float2bfloat16(v2), h3b = __float2bfloat16(v3);
            *(__nv_bfloat162*)(g_gahi + o0) = __halves2bfloat162(h0, h1b);
            *(__nv_bfloat162*)(g_gahi + o1) = __halves2bfloat162(h2, h3b);
            *(__nv_bfloat162*)(g_galo + o0) = __halves2bfloat162(
                __float2bfloat16(v0 - __bfloat162float(h0)),
                __float2bfloat16(v1 - __bfloat162float(h1b)));
            *(__nv_bfloat162*)(g_galo + o1) = __halves2bfloat162(
                __float2bfloat16(v2 - __bfloat162float(h2)),
                __float2bfloat16(v3 - __bfloat162float(h3b)));
        }
    }
}

// ---------------- launch ----------------
extern "C" void kernel_launch(void* const* d_in, const int* in_sizes, int n_in,
                              void* d_out, int out_size)
{
    const float* x      = (const float*)d_in[0];
    const float* w_qkv  = (const float*)d_in[1];
    const float* w_gate = (const float*)d_in[2];
    const float* w_out  = (const float*)d_in[3];
    const float* slopes = (const float*)d_in[4];
    float* out = (float*)d_out;

    float *qkv_p, *gate_p;
    cudaGetSymbolAddress((void**)&qkv_p,  g_qkv);
    cudaGetSymbolAddress((void**)&gate_p, g_gate);

    __nv_bfloat16 *xhi, *xlo, *wqh, *wql, *wgh, *wgl, *woh, *wol, *gah, *gal;
    cudaGetSymbolAddress((void**)&xhi, g_xhi);
    cudaGetSymbolAddress((void**)&xlo, g_xlo);
    cudaGetSymbolAddress((void**)&wqh, g_wqkvT_hi);
    cudaGetSymbolAddress((void**)&wql, g_wqkvT_lo);
    cudaGetSymbolAddress((void**)&wgh, g_wgateT_hi);
    cudaGetSymbolAddress((void**)&wgl, g_wgateT_lo);
    cudaGetSymbolAddress((void**)&woh, g_woutT_hi);
    cudaGetSymbolAddress((void**)&wol, g_woutT_lo);
    cudaGetSymbolAddress((void**)&gah, g_gahi);
    cudaGetSymbolAddress((void**)&gal, g_galo);

    cudaFuncSetAttribute(mma_gemm<EPI_SILU>,
                         cudaFuncAttributeMaxDynamicSharedMemorySize, GEMM_SMEM);
    cudaFuncSetAttribute(mma_gemm<EPI_SIGMOID>,
                         cudaFuncAttributeMaxDynamicSharedMemorySize, GEMM_SMEM);
    cudaFuncSetAttribute(mma_gemm<EPI_NONE>,
                         cudaFuncAttributeMaxDynamicSharedMemorySize, GEMM_SMEM);
    cudaFuncSetAttribute(attn_mma,
                         cudaFuncAttributeMaxDynamicSharedMemorySize, A_SMEM);
    cudaFuncSetAttribute(kvdelta_mma,
                         cudaFuncAttributeMaxDynamicSharedMemorySize, KD_SMEM);

    // 0) splits + transposes + decay tables
    {
        int n4 = MM * HIDN / 4;
        split_kernel<<<n4 / 256, 256>>>(x, xhi, xlo, n4);
        dim3 blk(32, 8);
        transp_split_kernel<<<dim3(QKVN / 32, HIDN / 32), blk>>>(w_qkv,  wqh, wql, HIDN, QKVN);
        transp_split_kernel<<<dim3(HIDN / 32, HIDN / 32), blk>>>(w_gate, wgh, wgl, HIDN, HIDN);
        transp_split_kernel<<<dim3(HIDN / 32, HIDN / 32), blk>>>(w_out,  woh, wol, HIDN, HIDN);
        dectab_kernel<<<NH, CC>>>(slopes);
    }
    // 1) qkv = silu(x @ w_qkv)
    mma_gemm<EPI_SILU><<<dim3(QKVN / 256, MM / 128), 512, GEMM_SMEM>>>(
        xhi, xlo, wqh, wql, qkv_p, MM, QKVN);
    // 2) per-head splits
    splitqkv_norm<<<(BB * SS * NH * 32) / 256, 256>>>();
    {
        dim3 blk(32, 8);
        trans_split_head<<<dim3(SS / 32, HD / 32, BB * NH), blk>>>();
    }
    // 3) gate = sigmoid(x @ w_gate)
    mma_gemm<EPI_SIGMOID><<<dim3(HIDN / 256, MM / 128), 512, GEMM_SMEM>>>(
        xhi, xlo, wgh, wgl, gate_p, MM, HIDN);
    // 4) attention pipeline
    kvdelta_mma<<<BB * NH * NCC, 256, KD_SMEM>>>();
    scan_kernel<<<BB * NH * 64, 256>>>(slopes);
    {
        dim3 blk(32, 8);
        kvsplitT_kernel<<<dim3(HD / 32, HD / 32, BB * NH * NCC), blk>>>();
    }
    attn_mma<<<dim3(BB * NH * NCC, 2), 256, A_SMEM>>>(slopes);
    // 5) out = (gate*attn) @ w_out
    mma_gemm<EPI_NONE><<<dim3(HIDN / 256, MM / 128), 512, GEMM_SMEM>>>(
        gah, gal, woh, wol, out, MM, HIDN);
}

// round 9
// speedup vs baseline: 1.2723x; 1.2723x over previous
#include <cuda_runtime.h>
#include <cuda_bf16.h>
#include <cuda_fp16.h>
#include <math.h>
#include <stdint.h>

// ---------------- problem constants ----------------
#define BB   2
#define SS   4096
#define HIDN 2048
#define NH   16
#define HD   128
#define CC   256
#define NCC  16
#define MM   (BB*SS)          // 8192
#define QKVN (3*HIDN)         // 6144
#define GK   HIDN
#define BKC  64
#define NCHUNK (GK/BKC)       // 32

// ---------------- device scratch ----------------
__device__ float g_qkv   [(size_t)MM * QKVN];
__device__ float g_gate  [(size_t)MM * HIDN];
__device__ float g_kvdelta[(size_t)BB*NH*NCC*HD*HD];
__device__ float g_kvstate[(size_t)BB*NH*NCC*HD*HD];

// fp16 2-pass operands for GEMM1/2
__device__ __half g_xh[(size_t)MM*HIDN], g_xl[(size_t)MM*HIDN];
__device__ __half g_wqkvT_h[(size_t)QKVN*HIDN];
__device__ __half g_wgateT_h[(size_t)HIDN*HIDN];

// bf16 3-pass operands for GEMM3
__device__ __nv_bfloat16 g_woutT_hi[(size_t)HIDN*HIDN], g_woutT_lo[(size_t)HIDN*HIDN];
__device__ __nv_bfloat16 g_gahi[(size_t)MM*HIDN],       g_galo[(size_t)MM*HIDN];

#define PHSZ ((size_t)BB*NH*SS*HD)
__device__ __nv_bfloat16 g_q_hi [PHSZ], g_q_lo [PHSZ];    // [bh][s][d]
__device__ __nv_bfloat16 g_k_hi [PHSZ], g_k_lo [PHSZ];    // [bh][s][d]
__device__ __nv_bfloat16 g_kdT_hi[PHSZ], g_kdT_lo[PHSZ];  // [bh][d][s]
__device__ __nv_bfloat16 g_vT_hi [PHSZ], g_vT_lo [PHSZ];  // [bh][d][s]
__device__ __nv_bfloat16 g_kvsT_hi[(size_t)BB*NH*NCC*HD*HD], g_kvsT_lo[(size_t)BB*NH*NCC*HD*HD];
__device__ float g_qdectab[NH*CC], g_kdectab[NH*CC];

// ---------------- epilogues ----------------
#define EPI_SILU    0
#define EPI_SIGMOID 1
#define EPI_NONE    2

__device__ __forceinline__ float apply_epi(float x, int mode) {
    if (mode == EPI_SILU)    return x / (1.0f + expf(-x));
    if (mode == EPI_SIGMOID) return 1.0f / (1.0f + expf(-x));
    return x;
}

// ---------------- base-ISA tensor-core helpers ----------------
__device__ __forceinline__ uint32_t smem_u32(const void* p) {
    uint32_t a;
    asm("{ .reg .u64 t; cvta.to.shared.u64 t, %1; cvt.u32.u64 %0, t; }" : "=r"(a) : "l"(p));
    return a;
}
__device__ __forceinline__ void cpasync16(uint32_t saddr, const void* g) {
    asm volatile("cp.async.cg.shared.global [%0], [%1], 16;" :: "r"(saddr), "l"(g));
}
__device__ __forceinline__ void cp_commit() {
    asm volatile("cp.async.commit_group;" ::: "memory");
}
template<int N> __device__ __forceinline__ void cp_wait() {
    asm volatile("cp.async.wait_group %0;" :: "n"(N) : "memory");
}
__device__ __forceinline__ void ldm_x4(uint32_t* r, uint32_t addr) {
    asm volatile("ldmatrix.sync.aligned.m8n8.x4.shared.b16 {%0,%1,%2,%3}, [%4];"
                 : "=r"(r[0]), "=r"(r[1]), "=r"(r[2]), "=r"(r[3]) : "r"(addr));
}
__device__ __forceinline__ void ldm_x2(uint32_t* r, uint32_t addr) {
    asm volatile("ldmatrix.sync.aligned.m8n8.x2.shared.b16 {%0,%1}, [%2];"
                 : "=r"(r[0]), "=r"(r[1]) : "r"(addr));
}
__device__ __forceinline__ void mma16816(float* c, const uint32_t* a, const uint32_t* b) {
    asm volatile(
        "mma.sync.aligned.m16n8k16.row.col.f32.bf16.bf16.f32 "
        "{%0,%1,%2,%3},{%4,%5,%6,%7},{%8,%9},{%0,%1,%2,%3};"
        : "+f"(c[0]), "+f"(c[1]), "+f"(c[2]), "+f"(c[3])
        : "r"(a[0]), "r"(a[1]), "r"(a[2]), "r"(a[3]), "r"(b[0]), "r"(b[1]));
}
__device__ __forceinline__ void mma16816h(float* c, const uint32_t* a, const uint32_t* b) {
    asm volatile(
        "mma.sync.aligned.m16n8k16.row.col.f32.f16.f16.f32 "
        "{%0,%1,%2,%3},{%4,%5,%6,%7},{%8,%9},{%0,%1,%2,%3};"
        : "+f"(c[0]), "+f"(c[1]), "+f"(c[2]), "+f"(c[3])
        : "r"(a[0]), "r"(a[1]), "r"(a[2]), "r"(a[3]), "r"(b[0]), "r"(b[1]));
}

#define LDSW   144

// ---------------- fp16 2-pass GEMM: C = (Ah+Al) @ Bh^T, tile 128x256, 512 thr ----------------
// smem per buffer: Ahi(128x144) Alo(128x144) B(256x144)
#define HA_SZ  (128 * LDSW)               // 18432
#define HB_SZ  (256 * LDSW)               // 36864
#define HBUF   (2 * HA_SZ + HB_SZ)        // 73728
#define GEMMH_SMEM (2 * HBUF)             // 147456

template<int EPI>
__global__ __launch_bounds__(512) void mma_gemm_h(
    const __half* __restrict__ Ahi, const __half* __restrict__ Alo,
    const __half* __restrict__ Bh,
    float* __restrict__ C, int M, int N)
{
    extern __shared__ char smraw[];
    const uint32_t sb = smem_u32(smraw);

    const int tid  = threadIdx.x;
    const int lane = tid & 31;
    const int wid  = tid >> 5;            // 0..15
    const int bm = blockIdx.y * 128;
    const int bn = blockIdx.x * 256;
    const int wm = (wid >> 3) * 64;
    const int wn = (wid & 7) * 32;

    auto prefetch = [&](int c, int buf) {
        const uint32_t bbase = sb + buf * HBUF;
        const int k0 = c * BKC;
        // A: 1024 sectors, 2/thread
        #pragma unroll
        for (int i = 0; i < 2; ++i) {
            int idx = tid + 512 * i;
            int row = idx >> 3, sec = idx & 7;
            const uint32_t so = row * LDSW + sec * 16;
            const size_t ga = (size_t)(bm + row) * GK + k0 + sec * 8;
            cpasync16(bbase + 0 * HA_SZ + so, Ahi + ga);
            cpasync16(bbase + 1 * HA_SZ + so, Alo + ga);
        }
        // B: 2048 sectors, 4/thread
        #pragma unroll
        for (int i = 0; i < 4; ++i) {
            int idx = tid + 512 * i;
            int row = idx >> 3, sec = idx & 7;
            const uint32_t so = row * LDSW + sec * 16;
            const size_t gb = (size_t)(bn + row) * GK + k0 + sec * 8;
            cpasync16(bbase + 2 * HA_SZ + so, Bh + gb);
        }
        cp_commit();
    };

    float acc[4][4][4];
    #pragma unroll
    for (int mi = 0; mi < 4; ++mi)
        #pragma unroll
        for (int ni = 0; ni < 4; ++ni)
            #pragma unroll
            for (int r = 0; r < 4; ++r) acc[mi][ni][r] = 0.0f;

    const uint32_t aOff = (uint32_t)(wm + (lane & 15)) * LDSW + (lane >> 4) * 16;
    const uint32_t bOff = (uint32_t)(wn + (lane & 7))  * LDSW + ((lane >> 3) & 1) * 16;

    prefetch(0, 0);

    for (int c = 0; c < NCHUNK; ++c) {
        const int cur = c & 1;
        if (c + 1 < NCHUNK) prefetch(c + 1, cur ^ 1);
        if (c + 1 < NCHUNK) cp_wait<1>(); else cp_wait<0>();
        __syncthreads();

        const uint32_t bbase = sb + cur * HBUF;
        #pragma unroll
        for (int ks = 0; ks < 4; ++ks) {
            const uint32_t kso = ks * 32;
            uint32_t aH[4][4], aL[4][4], bF[4][2];
            #pragma unroll
            for (int mi = 0; mi < 4; ++mi) {
                ldm_x4(aH[mi], bbase + 0 * HA_SZ + aOff + mi * 16 * LDSW + kso);
                ldm_x4(aL[mi], bbase + 1 * HA_SZ + aOff + mi * 16 * LDSW + kso);
            }
            #pragma unroll
            for (int ni = 0; ni < 4; ++ni)
                ldm_x2(bF[ni], bbase + 2 * HA_SZ + bOff + ni * 8 * LDSW + kso);
            #pragma unroll
            for (int mi = 0; mi < 4; ++mi)
                #pragma unroll
                for (int ni = 0; ni < 4; ++ni)
                    mma16816h(acc[mi][ni], aH[mi], bF[ni]);
            #pragma unroll
            for (int mi = 0; mi < 4; ++mi)
                #pragma unroll
                for (int ni = 0; ni < 4; ++ni)
                    mma16816h(acc[mi][ni], aL[mi], bF[ni]);
        }
        __syncthreads();
    }

    const int erow = lane >> 2;
    const int ecol = 2 * (lane & 3);
    #pragma unroll
    for (int mi = 0; mi < 4; ++mi) {
        #pragma unroll
        for (int ni = 0; ni < 4; ++ni) {
            const int gr0 = bm + wm + mi * 16 + erow;
            const int gc  = bn + wn + ni * 8 + ecol;
            float2 v0, v1;
            v0.x = apply_epi(acc[mi][ni][0], EPI);
            v0.y = apply_epi(acc[mi][ni][1], EPI);
            v1.x = apply_epi(acc[mi][ni][2], EPI);
            v1.y = apply_epi(acc[mi][ni][3], EPI);
            *(float2*)(C + (size_t)gr0 * N + gc)       = v0;
            *(float2*)(C + (size_t)(gr0 + 8) * N + gc) = v1;
        }
    }
}

// ---------------- bf16 3-pass GEMM (validated; used for GEMM3) ----------------
#define GA_SZ  (128 * LDSW)               // 18432
#define GB_SZ  (256 * LDSW)               // 36864
#define GBUF   (2 * GA_SZ + 2 * GB_SZ)    // 110592
#define GEMM_SMEM (2 * GBUF)              // 221184

template<int EPI>
__global__ __launch_bounds__(512) void mma_gemm(
    const __nv_bfloat16* __restrict__ Ahi, const __nv_bfloat16* __restrict__ Alo,
    const __nv_bfloat16* __restrict__ Bhi, const __nv_bfloat16* __restrict__ Blo,
    float* __restrict__ C, int M, int N)
{
    extern __shared__ char smraw[];
    const uint32_t sb = smem_u32(smraw);

    const int tid  = threadIdx.x;
    const int lane = tid & 31;
    const int wid  = tid >> 5;
    const int bm = blockIdx.y * 128;
    const int bn = blockIdx.x * 256;
    const int wm = (wid >> 3) * 64;
    const int wn = (wid & 7) * 32;

    auto prefetch = [&](int c, int buf) {
        const uint32_t bbase = sb + buf * GBUF;
        const int k0 = c * BKC;
        #pragma unroll
        for (int i = 0; i < 2; ++i) {
            int idx = tid + 512 * i;
            int row = idx >> 3, sec = idx & 7;
            const uint32_t so = row * LDSW + sec * 16;
            const size_t ga = (size_t)(bm + row) * GK + k0 + sec * 8;
            cpasync16(bbase + 0 * GA_SZ + so, Ahi + ga);
            cpasync16(bbase + 1 * GA_SZ + so, Alo + ga);
        }
        #pragma unroll
        for (int i = 0; i < 4; ++i) {
            int idx = tid + 512 * i;
            int row = idx >> 3, sec = idx & 7;
            const uint32_t so = row * LDSW + sec * 16;
            const size_t gb = (size_t)(bn + row) * GK + k0 + sec * 8;
            cpasync16(bbase + 2 * GA_SZ + so, Bhi + gb);
            cpasync16(bbase + 2 * GA_SZ + GB_SZ + so, Blo + gb);
        }
        cp_commit();
    };

    float acc[4][4][4];
    #pragma unroll
    for (int mi = 0; mi < 4; ++mi)
        #pragma unroll
        for (int ni = 0; ni < 4; ++ni)
            #pragma unroll
            for (int r = 0; r < 4; ++r) acc[mi][ni][r] = 0.0f;

    const uint32_t aOff = (uint32_t)(wm + (lane & 15)) * LDSW + (lane >> 4) * 16;
    const uint32_t bOff = (uint32_t)(wn + (lane & 7))  * LDSW + ((lane >> 3) & 1) * 16;

    prefetch(0, 0);

    for (int c = 0; c < NCHUNK; ++c) {
        const int cur = c & 1;
        if (c + 1 < NCHUNK) prefetch(c + 1, cur ^ 1);
        if (c + 1 < NCHUNK) cp_wait<1>(); else cp_wait<0>();
        __syncthreads();

        const uint32_t bbase = sb + cur * GBUF;
        #pragma unroll
        for (int ks = 0; ks < 4; ++ks) {
            const uint32_t kso = ks * 32;
            uint32_t aH[4][4], aL[4][4], bH[4][2], bL[4][2];
            #pragma unroll
            for (int mi = 0; mi < 4; ++mi) {
                ldm_x4(aH[mi], bbase + 0 * GA_SZ + aOff + mi * 16 * LDSW + kso);
                ldm_x4(aL[mi], bbase + 1 * GA_SZ + aOff + mi * 16 * LDSW + kso);
            }
            #pragma unroll
            for (int ni = 0; ni < 4; ++ni) {
                ldm_x2(bH[ni], bbase + 2 * GA_SZ + bOff + ni * 8 * LDSW + kso);
                ldm_x2(bL[ni], bbase + 2 * GA_SZ + GB_SZ + bOff + ni * 8 * LDSW + kso);
            }
            #pragma unroll
            for (int mi = 0; mi < 4; ++mi)
                #pragma unroll
                for (int ni = 0; ni < 4; ++ni)
                    mma16816(acc[mi][ni], aH[mi], bH[ni]);
            #pragma unroll
            for (int mi = 0; mi < 4; ++mi)
                #pragma unroll
                for (int ni = 0; ni < 4; ++ni)
                    mma16816(acc[mi][ni], aH[mi], bL[ni]);
            #pragma unroll
            for (int mi = 0; mi < 4; ++mi)
                #pragma unroll
                for (int ni = 0; ni < 4; ++ni)
                    mma16816(acc[mi][ni], aL[mi], bH[ni]);
        }
        __syncthreads();
    }

    const int erow = lane >> 2;
    const int ecol = 2 * (lane & 3);
    #pragma unroll
    for (int mi = 0; mi < 4; ++mi) {
        #pragma unroll
        for (int ni = 0; ni < 4; ++ni) {
            const int gr0 = bm + wm + mi * 16 + erow;
            const int gc  = bn + wn + ni * 8 + ecol;
            float2 v0, v1;
            v0.x = apply_epi(acc[mi][ni][0], EPI);
            v0.y = apply_epi(acc[mi][ni][1], EPI);
            v1.x = apply_epi(acc[mi][ni][2], EPI);
            v1.y = apply_epi(acc[mi][ni][3], EPI);
            *(float2*)(C + (size_t)gr0 * N + gc)       = v0;
            *(float2*)(C + (size_t)(gr0 + 8) * N + gc) = v1;
        }
    }
}

// ---------------- conversion kernels ----------------
__device__ __forceinline__ void split_store4(
    __nv_bfloat16* hi, __nv_bfloat16* lo, size_t o, float4 v, float scale)
{
    float a[4] = {v.x * scale, v.y * scale, v.z * scale, v.w * scale};
    __nv_bfloat16 h[4], l[4];
    #pragma unroll
    for (int j = 0; j < 4; j++) {
        h[j] = __float2bfloat16(a[j]);
        l[j] = __float2bfloat16(a[j] - __bfloat162float(h[j]));
    }
    *(__nv_bfloat162*)(hi + o)     = __halves2bfloat162(h[0], h[1]);
    *(__nv_bfloat162*)(hi + o + 2) = __halves2bfloat162(h[2], h[3]);
    *(__nv_bfloat162*)(lo + o)     = __halves2bfloat162(l[0], l[1]);
    *(__nv_bfloat162*)(lo + o + 2) = __halves2bfloat162(l[2], l[3]);
}

// x fp32 -> fp16 hi/lo
__global__ __launch_bounds__(256) void splith_kernel(
    const float* __restrict__ in, __half* __restrict__ hi,
    __half* __restrict__ lo, int n4)
{
    int i = blockIdx.x * 256 + threadIdx.x;
    if (i >= n4) return;
    float4 v = ((const float4*)in)[i];
    float a[4] = {v.x, v.y, v.z, v.w};
    __half h[4], l[4];
    #pragma unroll
    for (int j = 0; j < 4; j++) {
        h[j] = __float2half(a[j]);
        l[j] = __float2half(a[j] - __half2float(h[j]));
    }
    size_t o = (size_t)i * 4;
    *(__half2*)(hi + o)     = __halves2half2(h[0], h[1]);
    *(__half2*)(hi + o + 2) = __halves2half2(h[2], h[3]);
    *(__half2*)(lo + o)     = __halves2half2(l[0], l[1]);
    *(__half2*)(lo + o + 2) = __halves2half2(l[2], l[3]);
}

// w [K,N] fp32 -> wT [N,K] single fp16
__global__ void transp_half_kernel(
    const float* __restrict__ w, __half* __restrict__ t, int K, int N)
{
    __shared__ float ts[32][33];
    const int n0 = blockIdx.x * 32, k0 = blockIdx.y * 32;
    const int x = threadIdx.x, y = threadIdx.y;
    #pragma unroll
    for (int r = 0; r < 32; r += 8)
        ts[y + r][x] = w[(size_t)(k0 + y + r) * N + n0 + x];
    __syncthreads();
    #pragma unroll
    for (int r = 0; r < 32; r += 8) {
        size_t o = (size_t)(n0 + y + r) * K + k0 + x;
        t[o] = __float2half(ts[x][y + r]);
    }
}

// w [K,N] fp32 -> wT hi/lo [N,K] bf16 (GEMM3)
__global__ __launch_bounds__(256) void transp_split_kernel(
    const float* __restrict__ w, __nv_bfloat16* __restrict__ thi,
    __nv_bfloat16* __restrict__ tlo, int K, int N)
{
    __shared__ float t[32][33];
    const int n0 = blockIdx.x * 32, k0 = blockIdx.y * 32;
    const int x = threadIdx.x, y = threadIdx.y;
    #pragma unroll
    for (int r = 0; r < 32; r += 8)
        t[y + r][x] = w[(size_t)(k0 + y + r) * N + n0 + x];
    __syncthreads();
    #pragma unroll
    for (int r = 0; r < 32; r += 8) {
        float v = t[x][y + r];
        __nv_bfloat16 h = __float2bfloat16(v);
        __nv_bfloat16 l = __float2bfloat16(v - __bfloat162float(h));
        size_t o = (size_t)(n0 + y + r) * K + k0 + x;
        thi[o] = h;
        tlo[o] = l;
    }
}

__global__ void dectab_kernel(const float* __restrict__ slopes)
{
    int h = blockIdx.x, i = threadIdx.x;
    float s = slopes[h];
    g_qdectab[h * CC + i] = expf(-s * (float)(i + 1));
    g_kdectab[h * CC + i] = expf(-s * (float)(CC - 1 - i));
}

// g_qkv -> q, k in [bh][s][d] bf16 split
__global__ __launch_bounds__(256) void splitqkv_norm()
{
    int idx = blockIdx.x * 256 + threadIdx.x;
    int d4 = idx & 31; int rest = idx >> 5;
    int h = rest & 15; rest >>= 4;
    int s = rest & 4095; int b = rest >> 12;

    size_t qo = (size_t)(b * SS + s) * QKVN + h * HD + d4 * 4;
    float4 q = *(const float4*)&g_qkv[qo];
    float4 k = *(const float4*)&g_qkv[qo + HIDN];

    size_t o = ((size_t)(b * NH + h) * SS + s) * HD + d4 * 4;
    split_store4(g_q_hi, g_q_lo, o, q, 1.0f);
    split_store4(g_k_hi, g_k_lo, o, k, 1.0f);
}

// g_qkv k,v -> kdT, vT in [bh][d][s] bf16 split
__global__ void trans_split_head()
{
    __shared__ float tk[32][33], tv[32][33];
    const int z  = blockIdx.z;
    const int b  = z >> 4, h = z & 15;
    const int s0 = blockIdx.x * 32;
    const int d0 = blockIdx.y * 32;
    const int x = threadIdx.x, y = threadIdx.y;

    #pragma unroll
    for (int r = 0; r < 32; r += 8) {
        size_t base = (size_t)(b * SS + s0 + y + r) * QKVN + h * HD + d0 + x;
        tk[y + r][x] = g_qkv[base + HIDN];
        tv[y + r][x] = g_qkv[base + 2 * HIDN];
    }
    __syncthreads();
    #pragma unroll
    for (int r = 0; r < 32; r += 8) {
        int d = d0 + y + r;
        int s = s0 + x;
        float kdec = g_kdectab[h * CC + (s & (CC - 1))];
        float kv = tk[x][y + r] * kdec;
        float vv = tv[x][y + r];
        size_t o = ((size_t)z * HD + d) * SS + s;
        __nv_bfloat16 h1 = __float2bfloat16(kv);
        g_kdT_hi[o] = h1;
        g_kdT_lo[o] = __float2bfloat16(kv - __bfloat162float(h1));
        __nv_bfloat16 h2 = __float2bfloat16(vv);
        g_vT_hi[o] = h2;
        g_vT_lo[o] = __float2bfloat16(vv - __bfloat162float(h2));
    }
}

// g_kvstate [bhn][d'][e] -> kvsT [bhn][e][d'] bf16 split
__global__ void kvsplitT_kernel()
{
    __shared__ float t[32][33];
    const int bhn = blockIdx.z;
    const int d0 = blockIdx.x * 32;
    const int e0 = blockIdx.y * 32;
    const int x = threadIdx.x, y = threadIdx.y;
    const size_t base = (size_t)bhn * HD * HD;

    #pragma unroll
    for (int r = 0; r < 32; r += 8)
        t[y + r][x] = g_kvstate[base + (size_t)(d0 + y + r) * HD + e0 + x];
    __syncthreads();
    #pragma unroll
    for (int r = 0; r < 32; r += 8) {
        float v = t[x][y + r];
        size_t o = base + (size_t)(e0 + y + r) * HD + d0 + x;
        __nv_bfloat16 h1 = __float2bfloat16(v);
        g_kvsT_hi[o] = h1;
        g_kvsT_lo[o] = __float2bfloat16(v - __bfloat162float(h1));
    }
}

// ---------------- kvdelta via HMMA (double-buffered) ----------------
#define KD_MAT  18432
#define KD_BUF  (4 * KD_MAT)          // 73728
#define KD_SMEM (2 * KD_BUF)          // 147456

__global__ __launch_bounds__(256) void kvdelta_mma()
{
    extern __shared__ char smraw[];
    const uint32_t sb = smem_u32(smraw);

    const int blk = blockIdx.x;
    const int n  = blk & (NCC - 1);
    const int bh = blk >> 4;
    const size_t colb = (size_t)bh * HD;

    const int tid = threadIdx.x, lane = tid & 31, wid = tid >> 5;
    const int wm = (wid >> 2) * 64;
    const int wn = (wid & 3) * 32;

    auto prefetch = [&](int kt, int buf) {
        const uint32_t bbase = sb + buf * KD_BUF;
        const int k0 = n * CC + kt * 64;
        #pragma unroll
        for (int it = 0; it < 4; ++it) {
            int idx = tid + 256 * it;
            int row = idx >> 3, sec = idx & 7;
            size_t g = (colb + row) * SS + k0 + sec * 8;
            uint32_t so = row * 144 + sec * 16;
            cpasync16(bbase + 0 * KD_MAT + so, g_kdT_hi + g);
            cpasync16(bbase + 1 * KD_MAT + so, g_kdT_lo + g);
            cpasync16(bbase + 2 * KD_MAT + so, g_vT_hi + g);
            cpasync16(bbase + 3 * KD_MAT + so, g_vT_lo + g);
        }
        cp_commit();
    };

    float acc[4][4][4];
    #pragma unroll
    for (int mi = 0; mi < 4; ++mi)
        #pragma unroll
        for (int ni = 0; ni < 4; ++ni)
            #pragma unroll
            for (int r = 0; r < 4; ++r) acc[mi][ni][r] = 0.0f;

    prefetch(0, 0);

    for (int kt = 0; kt < 4; ++kt) {
        const int cur = kt & 1;
        if (kt + 1 < 4) prefetch(kt + 1, cur ^ 1);
        if (kt + 1 < 4) cp_wait<1>(); else cp_wait<0>();
        __syncthreads();

        const uint32_t bbase = sb + cur * KD_BUF;
        #pragma unroll
        for (int ks = 0; ks < 4; ++ks) {
            uint32_t aH[4][4], aL[4][4], bH[4][2], bL[4][2];
            const uint32_t ao = (uint32_t)(lane & 15) * 144 + (lane >> 4) * 16 + ks * 32;
            #pragma unroll
            for (int mi = 0; mi < 4; ++mi) {
                ldm_x4(aH[mi], bbase + 0 * KD_MAT + (wm + mi * 16) * 144 + ao);
                ldm_x4(aL[mi], bbase + 1 * KD_MAT + (wm + mi * 16) * 144 + ao);
            }
            const uint32_t bo = (uint32_t)(lane & 7) * 144 + ((lane >> 3) & 1) * 16 + ks * 32;
            #pragma unroll
            for (int ni = 0; ni < 4; ++ni) {
                ldm_x2(bH[ni], bbase + 2 * KD_MAT + (wn + ni * 8) * 144 + bo);
                ldm_x2(bL[ni], bbase + 3 * KD_MAT + (wn + ni * 8) * 144 + bo);
            }
            #pragma unroll
            for (int mi = 0; mi < 4; ++mi)
                #pragma unroll
                for (int ni = 0; ni < 4; ++ni)
                    mma16816(acc[mi][ni], aH[mi], bH[ni]);
            #pragma unroll
            for (int mi = 0; mi < 4; ++mi)
                #pragma unroll
                for (int ni = 0; ni < 4; ++ni)
                    mma16816(acc[mi][ni], aH[mi], bL[ni]);
            #pragma unroll
            for (int mi = 0; mi < 4; ++mi)
                #pragma unroll
                for (int ni = 0; ni < 4; ++ni)
                    mma16816(acc[mi][ni], aL[mi], bH[ni]);
        }
        __syncthreads();
    }

    const int erow = lane >> 2, ecol = 2 * (lane & 3);
    float* out = &g_kvdelta[(size_t)blk * HD * HD];
    #pragma unroll
    for (int mi = 0; mi < 4; ++mi) {
        #pragma unroll
        for (int ni = 0; ni < 4; ++ni) {
            int d = wm + mi * 16 + erow;
            int e = wn + ni * 8 + ecol;
            *(float2*)(out + (size_t)d * HD + e)       = make_float2(acc[mi][ni][0], acc[mi][ni][1]);
            *(float2*)(out + (size_t)(d + 8) * HD + e) = make_float2(acc[mi][ni][2], acc[mi][ni][3]);
        }
    }
}

// ---------------- scan (parallel) ----------------
__global__ __launch_bounds__(256) void scan_kernel(const float* __restrict__ slopes)
{
    const int gid = blockIdx.x * 256 + threadIdx.x;
    const int bh  = gid >> 14;
    const int p   = gid & 16383;
    const float bd = expf(-slopes[bh & (NH - 1)] * (float)CC);
    const size_t base = (size_t)bh * NCC * HD * HD + p;

    float st = 0.0f;
    #pragma unroll
    for (int nn = 0; nn < NCC; nn++) {
        g_kvstate[base + (size_t)nn * HD * HD] = st;
        st = bd * st + g_kvdelta[base + (size_t)nn * HD * HD];
    }
}

// ---------------- fused attention via HMMA (pipelined, inter-first) ----------------
#define A_QHI   0
#define A_QLO   34816
#define A_KHI   69632
#define A_KLO   87040
#define A_VT0   104448
#define A_VT1   141312
#define A_SHI   178176
#define A_SLO   196608
#define A_SMEM  215040
#define A_KVSHI 69632
#define A_KVSLO 178176

__global__ __launch_bounds__(256) void attn_mma(const float* __restrict__ slopes)
{
    extern __shared__ char smraw[];
    const uint32_t sb = smem_u32(smraw);
    __shared__ float sdec[CC];

    const int blk = blockIdx.x;
    const int itile = blockIdx.y;
    const int n  = blk & (NCC - 1);
    const int bh = blk >> 4;
    const int h  = bh & (NH - 1);
    const int b  = bh >> 4;
    const float s = slopes[h];

    const int tid = threadIdx.x, lane = tid & 31, wid = tid >> 5;
    sdec[tid] = expf(-s * (float)tid);
    const float fexp = expf(-s);

    const size_t rowb = (size_t)bh * SS + n * CC;
    const size_t colb = (size_t)bh * HD;
    const int i0 = itile * 128;

    // group 0: q tile + kvsT (inter operand)
    #pragma unroll
    for (int it = 0; it < 8; ++it) {
        int idx = tid + 256 * it;
        int row = idx >> 4, sec = idx & 15;
        size_t g = (rowb + i0 + row) * HD + sec * 8;
        uint32_t so = row * 272 + sec * 16;
        cpasync16(sb + A_QHI + so, g_q_hi + g);
        cpasync16(sb + A_QLO + so, g_q_lo + g);
    }
    {
        const size_t kvb = (size_t)blk * HD * HD;
        #pragma unroll
        for (int it = 0; it < 8; ++it) {
            int idx = tid + 256 * it;
            int row = idx >> 4, sec = idx & 15;
            size_t g = kvb + (size_t)row * HD + sec * 8;
            uint32_t so = row * 272 + sec * 16;
            cpasync16(sb + A_KVSHI + so, g_kvsT_hi + g);
            cpasync16(sb + A_KVSLO + so, g_kvsT_lo + g);
        }
    }
    cp_commit();

    // group 1: vT(j=0) into buf0
    #pragma unroll
    for (int it = 0; it < 4; ++it) {
        int idx = tid + 256 * it;
        int row = idx >> 3, sec = idx & 7;
        size_t g = (colb + row) * SS + n * CC + sec * 8;
        uint32_t so = row * 144 + sec * 16;
        cpasync16(sb + A_VT0 + so, g_vT_hi + g);
        cpasync16(sb + A_VT0 + 18432 + so, g_vT_lo + g);
    }
    cp_commit();

    const int wm  = (wid >> 2) * 64;
    const int wns = (wid & 3) * 16;
    const int wno = (wid & 3) * 32;
    const int erow = lane >> 2, ecol = 2 * (lane & 3);

    float oacc[4][4][4];
    #pragma unroll
    for (int mi = 0; mi < 4; ++mi)
        #pragma unroll
        for (int ni = 0; ni < 4; ++ni)
            #pragma unroll
            for (int r = 0; r < 4; ++r) oacc[mi][ni][r] = 0.0f;

    // ---- inter FIRST: oacc = q @ kvsT, then row-scale by qdec ----
    cp_wait<1>();
    __syncthreads();

    #pragma unroll
    for (int ks = 0; ks < 8; ++ks) {
        uint32_t aH[4][4], aL[4][4], bH[4][2], bL[4][2];
        const uint32_t ao = (uint32_t)(lane & 15) * 272 + (lane >> 4) * 16 + ks * 32;
        #pragma unroll
        for (int mi = 0; mi < 4; ++mi) {
            ldm_x4(aH[mi], sb + A_QHI + (wm + mi * 16) * 272 + ao);
            ldm_x4(aL[mi], sb + A_QLO + (wm + mi * 16) * 272 + ao);
        }
        const uint32_t bo = (uint32_t)(lane & 7) * 272 + ((lane >> 3) & 1) * 16 + ks * 32;
        #pragma unroll
        for (int ni = 0; ni < 4; ++ni) {
            ldm_x2(bH[ni], sb + A_KVSHI + (wno + ni * 8) * 272 + bo);
            ldm_x2(bL[ni], sb + A_KVSLO + (wno + ni * 8) * 272 + bo);
        }
        #pragma unroll
        for (int mi = 0; mi < 4; ++mi)
            #pragma unroll
            for (int ni = 0; ni < 4; ++ni)
                mma16816(oacc[mi][ni], aH[mi], bH[ni]);
        #pragma unroll
        for (int mi = 0; mi < 4; ++mi)
            #pragma unroll
            for (int ni = 0; ni < 4; ++ni)
                mma16816(oacc[mi][ni], aH[mi], bL[ni]);
        #pragma unroll
        for (int mi = 0; mi < 4; ++mi)
            #pragma unroll
            for (int ni = 0; ni < 4; ++ni)
                mma16816(oacc[mi][ni], aL[mi], bH[ni]);
    }
    #pragma unroll
    for (int mi = 0; mi < 4; ++mi) {
        const int il0 = wm + mi * 16 + erow;
        const float qd0 = sdec[i0 + il0] * fexp;
        const float qd1 = sdec[i0 + il0 + 8] * fexp;
        #pragma unroll
        for (int ni = 0; ni < 4; ++ni) {
            oacc[mi][ni][0] *= qd0;
            oacc[mi][ni][1] *= qd0;
            oacc[mi][ni][2] *= qd1;
            oacc[mi][ni][3] *= qd1;
        }
    }
    __syncthreads();

    // load k(0)
    #pragma unroll
    for (int it = 0; it < 4; ++it) {
        int idx = tid + 256 * it;
        int row = idx >> 4, sec = idx & 15;
        size_t g = (rowb + row) * HD + sec * 8;
        uint32_t so = row * 272 + sec * 16;
        cpasync16(sb + A_KHI + so, g_k_hi + g);
        cpasync16(sb + A_KLO + so, g_k_lo + g);
    }
    cp_commit();

    const int njt = 2 * (itile + 1);
    for (int jt = 0; jt < njt; ++jt) {
        const int j0 = jt * 64;
        const int cur = jt & 1;
        const uint32_t vtb = sb + (cur ? A_VT1 : A_VT0);

        cp_wait<0>();
        __syncthreads();

        // ---- S = q @ k^T ----
        float sacc[4][2][4];
        #pragma unroll
        for (int mi = 0; mi < 4; ++mi)
            #pragma unroll
            for (int ni = 0; ni < 2; ++ni)
                #pragma unroll
                for (int r = 0; r < 4; ++r) sacc[mi][ni][r] = 0.0f;

        #pragma unroll
        for (int ks = 0; ks < 8; ++ks) {
            uint32_t aH[4][4], aL[4][4], bH[2][2], bL[2][2];
            const uint32_t ao = (uint32_t)(lane & 15) * 272 + (lane >> 4) * 16 + ks * 32;
            #pragma unroll
            for (int mi = 0; mi < 4; ++mi) {
                ldm_x4(aH[mi], sb + A_QHI + (wm + mi * 16) * 272 + ao);
                ldm_x4(aL[mi], sb + A_QLO + (wm + mi * 16) * 272 + ao);
            }
            const uint32_t bo = (uint32_t)(lane & 7) * 272 + ((lane >> 3) & 1) * 16 + ks * 32;
            #pragma unroll
            for (int ni = 0; ni < 2; ++ni) {
                ldm_x2(bH[ni], sb + A_KHI + (wns + ni * 8) * 272 + bo);
                ldm_x2(bL[ni], sb + A_KLO + (wns + ni * 8) * 272 + bo);
            }
            #pragma unroll
            for (int mi = 0; mi < 4; ++mi)
                #pragma unroll
                for (int ni = 0; ni < 2; ++ni)
                    mma16816(sacc[mi][ni], aH[mi], bH[ni]);
            #pragma unroll
            for (int mi = 0; mi < 4; ++mi)
                #pragma unroll
                for (int ni = 0; ni < 2; ++ni)
                    mma16816(sacc[mi][ni], aH[mi], bL[ni]);
            #pragma unroll
            for (int mi = 0; mi < 4; ++mi)
                #pragma unroll
                for (int ni = 0; ni < 2; ++ni)
                    mma16816(sacc[mi][ni], aL[mi], bH[ni]);
        }

        // ---- decay + split S ----
        #pragma unroll
        for (int mi = 0; mi < 4; ++mi) {
            #pragma unroll
            for (int ni = 0; ni < 2; ++ni) {
                #pragma unroll
                for (int r = 0; r < 4; ++r) {
                    int il = wm + mi * 16 + erow + (r >> 1) * 8;
                    int jl = wns + ni * 8 + ecol + (r & 1);
                    int dd = (i0 + il) - (j0 + jl);
                    float val = (dd >= 0) ? sacc[mi][ni][r] * sdec[dd] : 0.0f;
                    __nv_bfloat16 hi = __float2bfloat16(val);
                    __nv_bfloat16 lo = __float2bfloat16(val - __bfloat162float(hi));
                    *(__nv_bfloat16*)(smraw + A_SHI + il * 144 + jl * 2) = hi;
                    *(__nv_bfloat16*)(smraw + A_SLO + il * 144 + jl * 2) = lo;
                }
            }
        }
        __syncthreads();

        // prefetch k(jt+1) and vT(jt+1)
        if (jt + 1 < njt) {
            const int jn = (jt + 1) * 64;
            #pragma unroll
            for (int it = 0; it < 4; ++it) {
                int idx = tid + 256 * it;
                int row = idx >> 4, sec = idx & 15;
                size_t g = (rowb + jn + row) * HD + sec * 8;
                uint32_t so = row * 272 + sec * 16;
                cpasync16(sb + A_KHI + so, g_k_hi + g);
                cpasync16(sb + A_KLO + so, g_k_lo + g);
            }
            const uint32_t vtn = sb + (cur ? A_VT0 : A_VT1);
            #pragma unroll
            for (int it = 0; it < 4; ++it) {
                int idx = tid + 256 * it;
                int row = idx >> 3, sec = idx & 7;
                size_t g = (colb + row) * SS + n * CC + jn + sec * 8;
                uint32_t so = row * 144 + sec * 16;
                cpasync16(vtn + so, g_vT_hi + g);
                cpasync16(vtn + 18432 + so, g_vT_lo + g);
            }
            cp_commit();
        }

        // ---- O += S̃ @ v ----
        #pragma unroll
        for (int ks = 0; ks < 4; ++ks) {
            uint32_t aH[4][4], aL[4][4], bH[4][2], bL[4][2];
            const uint32_t ao = (uint32_t)(lane & 15) * 144 + (lane >> 4) * 16 + ks * 32;
            #pragma unroll
            for (int mi = 0; mi < 4; ++mi) {
                ldm_x4(aH[mi], sb + A_SHI + (wm + mi * 16) * 144 + ao);
                ldm_x4(aL[mi], sb + A_SLO + (wm + mi * 16) * 144 + ao);
            }
            const uint32_t bo = (uint32_t)(lane & 7) * 144 + ((lane >> 3) & 1) * 16 + ks * 32;
            #pragma unroll
            for (int ni = 0; ni < 4; ++ni) {
                ldm_x2(bH[ni], vtb + (wno + ni * 8) * 144 + bo);
                ldm_x2(bL[ni], vtb + 18432 + (wno + ni * 8) * 144 + bo);
            }
            #pragma unroll
            for (int mi = 0; mi < 4; ++mi)
                #pragma unroll
                for (int ni = 0; ni < 4; ++ni)
                    mma16816(oacc[mi][ni], aH[mi], bH[ni]);
            #pragma unroll
            for (int mi = 0; mi < 4; ++mi)
                #pragma unroll
                for (int ni = 0; ni < 4; ++ni)
                    mma16816(oacc[mi][ni], aH[mi], bL[ni]);
            #pragma unroll
            for (int mi = 0; mi < 4; ++mi)
                #pragma unroll
                for (int ni = 0; ni < 4; ++ni)
                    mma16816(oacc[mi][ni], aL[mi], bH[ni]);
        }
    }

    // ---- epilogue: gate-fused split store ----
    #pragma unroll
    for (int mi = 0; mi < 4; ++mi) {
        #pragma unroll
        for (int ni = 0; ni < 4; ++ni) {
            int il = wm + mi * 16 + erow;
            int e  = wno + ni * 8 + ecol;
            size_t o0 = (size_t)(b * SS + n * CC + i0 + il) * HIDN + h * HD + e;
            size_t o1 = o0 + 8 * HIDN;
            float2 g0 = *(const float2*)(g_gate + o0);
            float2 g1 = *(const float2*)(g_gate + o1);
            float v0 = oacc[mi][ni][0] * g0.x;
            float v1 = oacc[mi][ni][1] * g0.y;
            float v2 = oacc[mi][ni][2] * g1.x;
            float v3 = oacc[mi][ni][3] * g1.y;
            __nv_bfloat16 h0 = __float2bfloat16(v0), h1b = __float2bfloat16(v1);
            __nv_bfloat16 h2 = __float2bfloat16(v2), h3b = __float2bfloat16(v3);
            *(__nv_bfloat162*)(g_gahi + o0) = __halves2bfloat162(h0, h1b);
            *(__nv_bfloat162*)(g_gahi + o1) = __halves2bfloat162(h2, h3b);
            *(__nv_bfloat162*)(g_galo + o0) = __halves2bfloat162(
                __float2bfloat16(v0 - __bfloat162float(h0)),
                __float2bfloat16(v1 - __bfloat162float(h1b)));
            *(__nv_bfloat162*)(g_galo + o1) = __halves2bfloat162(
                __float2bfloat16(v2 - __bfloat162float(h2)),
                __float2bfloat16(v3 - __bfloat162float(h3b)));
        }
    }
}

// ---------------- launch ----------------
extern "C" void kernel_launch(void* const* d_in, const int* in_sizes, int n_in,
                              void* d_out, int out_size)
{
    const float* x      = (const float*)d_in[0];
    const float* w_qkv  = (const float*)d_in[1];
    const float* w_gate = (const float*)d_in[2];
    const float* w_out  = (const float*)d_in[3];
    const float* slopes = (const float*)d_in[4];
    float* out = (float*)d_out;

    float *qkv_p, *gate_p;
    cudaGetSymbolAddress((void**)&qkv_p,  g_qkv);
    cudaGetSymbolAddress((void**)&gate_p, g_gate);

    __half *xh, *xl, *wqh, *wgh;
    cudaGetSymbolAddress((void**)&xh,  g_xh);
    cudaGetSymbolAddress((void**)&xl,  g_xl);
    cudaGetSymbolAddress((void**)&wqh, g_wqkvT_h);
    cudaGetSymbolAddress((void**)&wgh, g_wgateT_h);

    __nv_bfloat16 *woh, *wol, *gah, *gal;
    cudaGetSymbolAddress((void**)&woh, g_woutT_hi);
    cudaGetSymbolAddress((void**)&wol, g_woutT_lo);
    cudaGetSymbolAddress((void**)&gah, g_gahi);
    cudaGetSymbolAddress((void**)&gal, g_galo);

    cudaFuncSetAttribute(mma_gemm_h<EPI_SILU>,
                         cudaFuncAttributeMaxDynamicSharedMemorySize, GEMMH_SMEM);
    cudaFuncSetAttribute(mma_gemm_h<EPI_SIGMOID>,
                         cudaFuncAttributeMaxDynamicSharedMemorySize, GEMMH_SMEM);
    cudaFuncSetAttribute(mma_gemm<EPI_NONE>,
                         cudaFuncAttributeMaxDynamicSharedMemorySize, GEMM_SMEM);
    cudaFuncSetAttribute(attn_mma,
                         cudaFuncAttributeMaxDynamicSharedMemorySize, A_SMEM);
    cudaFuncSetAttribute(kvdelta_mma,
                         cudaFuncAttributeMaxDynamicSharedMemorySize, KD_SMEM);

    // 0) splits + transposes + decay tables
    {
        int n4 = MM * HIDN / 4;
        splith_kernel<<<n4 / 256, 256>>>(x, xh, xl, n4);
        dim3 blk(32, 8);
        transp_half_kernel<<<dim3(QKVN / 32, HIDN / 32), blk>>>(w_qkv,  wqh, HIDN, QKVN);
        transp_half_kernel<<<dim3(HIDN / 32, HIDN / 32), blk>>>(w_gate, wgh, HIDN, HIDN);
        transp_split_kernel<<<dim3(HIDN / 32, HIDN / 32), blk>>>(w_out, woh, wol, HIDN, HIDN);
        dectab_kernel<<<NH, CC>>>(slopes);
    }
    // 1) qkv = silu(x @ w_qkv)   [fp16 2-pass]
    mma_gemm_h<EPI_SILU><<<dim3(QKVN / 256, MM / 128), 512, GEMMH_SMEM>>>(
        xh, xl, wqh, qkv_p, MM, QKVN);
    // 2) per-head splits
    splitqkv_norm<<<(BB * SS * NH * 32) / 256, 256>>>();
    {
        dim3 blk(32, 8);
        trans_split_head<<<dim3(SS / 32, HD / 32, BB * NH), blk>>>();
    }
    // 3) gate = sigmoid(x @ w_gate)   [fp16 2-pass]
    mma_gemm_h<EPI_SIGMOID><<<dim3(HIDN / 256, MM / 128), 512, GEMMH_SMEM>>>(
        xh, xl, wgh, gate_p, MM, HIDN);
    // 4) attention pipeline (bf16 3-pass)
    kvdelta_mma<<<BB * NH * NCC, 256, KD_SMEM>>>();
    scan_kernel<<<BB * NH * 64, 256>>>(slopes);
    {
        dim3 blk(32, 8);
        kvsplitT_kernel<<<dim3(HD / 32, HD / 32, BB * NH * NCC), blk>>>();
    }
    attn_mma<<<dim3(BB * NH * NCC, 2), 256, A_SMEM>>>(slopes);
    // 5) out = (gate*attn) @ w_out   [bf16 3-pass]
    mma_gemm<EPI_NONE><<<dim3(HIDN / 256, MM / 128), 512, GEMM_SMEM>>>(
        gah, gal, woh, wol, out, MM, HIDN);
}

// round 10
// speedup vs baseline: 1.4165x; 1.1133x over previous
#include <cuda_runtime.h>
#include <cuda_fp16.h>
#include <math.h>
#include <stdint.h>

// ---------------- problem constants ----------------
#define BB   2
#define SS   4096
#define HIDN 2048
#define NH   16
#define HD   128
#define CC   256
#define NCC  16
#define MM   (BB*SS)          // 8192
#define QKVN (3*HIDN)         // 6144
#define GK   HIDN
#define BKC  64
#define NCHUNK (GK/BKC)       // 32

// ---------------- device scratch ----------------
__device__ float g_qkv   [(size_t)MM * QKVN];
__device__ float g_gate  [(size_t)MM * HIDN];
__device__ float g_kvdelta[(size_t)BB*NH*NCC*HD*HD];
__device__ float g_kvstate[(size_t)BB*NH*NCC*HD*HD];

// fp16 2-pass GEMM operands
__device__ __half g_xh[(size_t)MM*HIDN], g_xl[(size_t)MM*HIDN];
__device__ __half g_wqkvT_h[(size_t)QKVN*HIDN];
__device__ __half g_wgateT_h[(size_t)HIDN*HIDN];
__device__ __half g_woutT_h[(size_t)HIDN*HIDN];
__device__ __half g_gah[(size_t)MM*HIDN], g_gal[(size_t)MM*HIDN];

// fp16 attention operands
#define PHSZ ((size_t)BB*NH*SS*HD)
__device__ __half g_q_hi [PHSZ], g_q_lo [PHSZ];   // [bh][s][d]
__device__ __half g_k    [PHSZ];                   // [bh][s][d] single
__device__ __half g_kdT_hi[PHSZ], g_kdT_lo[PHSZ]; // [bh][d][s]
__device__ __half g_vT   [PHSZ];                   // [bh][d][s] single
__device__ __half g_kvsT [(size_t)BB*NH*NCC*HD*HD]; // [bhn][e][d'] single
__device__ float g_qdectab[NH*CC], g_kdectab[NH*CC];

// ---------------- epilogues ----------------
#define EPI_SILU    0
#define EPI_SIGMOID 1
#define EPI_NONE    2

__device__ __forceinline__ float apply_epi(float x, int mode) {
    if (mode == EPI_SILU)    return x / (1.0f + expf(-x));
    if (mode == EPI_SIGMOID) return 1.0f / (1.0f + expf(-x));
    return x;
}

// ---------------- base-ISA tensor-core helpers ----------------
__device__ __forceinline__ uint32_t smem_u32(const void* p) {
    uint32_t a;
    asm("{ .reg .u64 t; cvta.to.shared.u64 t, %1; cvt.u32.u64 %0, t; }" : "=r"(a) : "l"(p));
    return a;
}
__device__ __forceinline__ void cpasync16(uint32_t saddr, const void* g) {
    asm volatile("cp.async.cg.shared.global [%0], [%1], 16;" :: "r"(saddr), "l"(g));
}
__device__ __forceinline__ void cp_commit() {
    asm volatile("cp.async.commit_group;" ::: "memory");
}
template<int N> __device__ __forceinline__ void cp_wait() {
    asm volatile("cp.async.wait_group %0;" :: "n"(N) : "memory");
}
__device__ __forceinline__ void ldm_x4(uint32_t* r, uint32_t addr) {
    asm volatile("ldmatrix.sync.aligned.m8n8.x4.shared.b16 {%0,%1,%2,%3}, [%4];"
                 : "=r"(r[0]), "=r"(r[1]), "=r"(r[2]), "=r"(r[3]) : "r"(addr));
}
__device__ __forceinline__ void ldm_x2(uint32_t* r, uint32_t addr) {
    asm volatile("ldmatrix.sync.aligned.m8n8.x2.shared.b16 {%0,%1}, [%2];"
                 : "=r"(r[0]), "=r"(r[1]) : "r"(addr));
}
__device__ __forceinline__ void mma16816h(float* c, const uint32_t* a, const uint32_t* b) {
    asm volatile(
        "mma.sync.aligned.m16n8k16.row.col.f32.f16.f16.f32 "
        "{%0,%1,%2,%3},{%4,%5,%6,%7},{%8,%9},{%0,%1,%2,%3};"
        : "+f"(c[0]), "+f"(c[1]), "+f"(c[2]), "+f"(c[3])
        : "r"(a[0]), "r"(a[1]), "r"(a[2]), "r"(a[3]), "r"(b[0]), "r"(b[1]));
}

#define LDSW   144

// ---------------- fp16 2-pass GEMM: C = (Ah+Al) @ Bh^T, tile 128x256, 512 thr ----------------
#define HA_SZ  (128 * LDSW)               // 18432
#define HB_SZ  (256 * LDSW)               // 36864
#define HBUF   (2 * HA_SZ + HB_SZ)        // 73728
#define GEMMH_SMEM (2 * HBUF)             // 147456

template<int EPI>
__global__ __launch_bounds__(512) void mma_gemm_h(
    const __half* __restrict__ Ahi, const __half* __restrict__ Alo,
    const __half* __restrict__ Bh,
    float* __restrict__ C, int M, int N)
{
    extern __shared__ char smraw[];
    const uint32_t sb = smem_u32(smraw);

    const int tid  = threadIdx.x;
    const int lane = tid & 31;
    const int wid  = tid >> 5;
    const int bm = blockIdx.y * 128;
    const int bn = blockIdx.x * 256;
    const int wm = (wid >> 3) * 64;
    const int wn = (wid & 7) * 32;

    auto prefetch = [&](int c, int buf) {
        const uint32_t bbase = sb + buf * HBUF;
        const int k0 = c * BKC;
        #pragma unroll
        for (int i = 0; i < 2; ++i) {
            int idx = tid + 512 * i;
            int row = idx >> 3, sec = idx & 7;
            const uint32_t so = row * LDSW + sec * 16;
            const size_t ga = (size_t)(bm + row) * GK + k0 + sec * 8;
            cpasync16(bbase + 0 * HA_SZ + so, Ahi + ga);
            cpasync16(bbase + 1 * HA_SZ + so, Alo + ga);
        }
        #pragma unroll
        for (int i = 0; i < 4; ++i) {
            int idx = tid + 512 * i;
            int row = idx >> 3, sec = idx & 7;
            const uint32_t so = row * LDSW + sec * 16;
            const size_t gb = (size_t)(bn + row) * GK + k0 + sec * 8;
            cpasync16(bbase + 2 * HA_SZ + so, Bh + gb);
        }
        cp_commit();
    };

    float acc[4][4][4];
    #pragma unroll
    for (int mi = 0; mi < 4; ++mi)
        #pragma unroll
        for (int ni = 0; ni < 4; ++ni)
            #pragma unroll
            for (int r = 0; r < 4; ++r) acc[mi][ni][r] = 0.0f;

    const uint32_t aOff = (uint32_t)(wm + (lane & 15)) * LDSW + (lane >> 4) * 16;
    const uint32_t bOff = (uint32_t)(wn + (lane & 7))  * LDSW + ((lane >> 3) & 1) * 16;

    prefetch(0, 0);

    for (int c = 0; c < NCHUNK; ++c) {
        const int cur = c & 1;
        if (c + 1 < NCHUNK) prefetch(c + 1, cur ^ 1);
        if (c + 1 < NCHUNK) cp_wait<1>(); else cp_wait<0>();
        __syncthreads();

        const uint32_t bbase = sb + cur * HBUF;
        #pragma unroll
        for (int ks = 0; ks < 4; ++ks) {
            const uint32_t kso = ks * 32;
            uint32_t aH[4][4], aL[4][4], bF[4][2];
            #pragma unroll
            for (int mi = 0; mi < 4; ++mi) {
                ldm_x4(aH[mi], bbase + 0 * HA_SZ + aOff + mi * 16 * LDSW + kso);
                ldm_x4(aL[mi], bbase + 1 * HA_SZ + aOff + mi * 16 * LDSW + kso);
            }
            #pragma unroll
            for (int ni = 0; ni < 4; ++ni)
                ldm_x2(bF[ni], bbase + 2 * HA_SZ + bOff + ni * 8 * LDSW + kso);
            #pragma unroll
            for (int mi = 0; mi < 4; ++mi)
                #pragma unroll
                for (int ni = 0; ni < 4; ++ni)
                    mma16816h(acc[mi][ni], aH[mi], bF[ni]);
            #pragma unroll
            for (int mi = 0; mi < 4; ++mi)
                #pragma unroll
                for (int ni = 0; ni < 4; ++ni)
                    mma16816h(acc[mi][ni], aL[mi], bF[ni]);
        }
        __syncthreads();
    }

    const int erow = lane >> 2;
    const int ecol = 2 * (lane & 3);
    #pragma unroll
    for (int mi = 0; mi < 4; ++mi) {
        #pragma unroll
        for (int ni = 0; ni < 4; ++ni) {
            const int gr0 = bm + wm + mi * 16 + erow;
            const int gc  = bn + wn + ni * 8 + ecol;
            float2 v0, v1;
            v0.x = apply_epi(acc[mi][ni][0], EPI);
            v0.y = apply_epi(acc[mi][ni][1], EPI);
            v1.x = apply_epi(acc[mi][ni][2], EPI);
            v1.y = apply_epi(acc[mi][ni][3], EPI);
            *(float2*)(C + (size_t)gr0 * N + gc)       = v0;
            *(float2*)(C + (size_t)(gr0 + 8) * N + gc) = v1;
        }
    }
}

// ---------------- conversion kernels ----------------
__device__ __forceinline__ void split_store4h(
    __half* hi, __half* lo, size_t o, float4 v, float scale)
{
    float a[4] = {v.x * scale, v.y * scale, v.z * scale, v.w * scale};
    __half h[4], l[4];
    #pragma unroll
    for (int j = 0; j < 4; j++) {
        h[j] = __float2half(a[j]);
        l[j] = __float2half(a[j] - __half2float(h[j]));
    }
    *(__half2*)(hi + o)     = __halves2half2(h[0], h[1]);
    *(__half2*)(hi + o + 2) = __halves2half2(h[2], h[3]);
    *(__half2*)(lo + o)     = __halves2half2(l[0], l[1]);
    *(__half2*)(lo + o + 2) = __halves2half2(l[2], l[3]);
}
__device__ __forceinline__ void store4h(__half* d, size_t o, float4 v)
{
    *(__half2*)(d + o)     = __halves2half2(__float2half(v.x), __float2half(v.y));
    *(__half2*)(d + o + 2) = __halves2half2(__float2half(v.z), __float2half(v.w));
}

// x fp32 -> fp16 hi/lo
__global__ __launch_bounds__(256) void splith_kernel(
    const float* __restrict__ in, __half* __restrict__ hi,
    __half* __restrict__ lo, int n4)
{
    int i = blockIdx.x * 256 + threadIdx.x;
    if (i >= n4) return;
    split_store4h(hi, lo, (size_t)i * 4, ((const float4*)in)[i], 1.0f);
}

// w [K,N] fp32 -> wT [N,K] single fp16
__global__ void transp_half_kernel(
    const float* __restrict__ w, __half* __restrict__ t, int K, int N)
{
    __shared__ float ts[32][33];
    const int n0 = blockIdx.x * 32, k0 = blockIdx.y * 32;
    const int x = threadIdx.x, y = threadIdx.y;
    #pragma unroll
    for (int r = 0; r < 32; r += 8)
        ts[y + r][x] = w[(size_t)(k0 + y + r) * N + n0 + x];
    __syncthreads();
    #pragma unroll
    for (int r = 0; r < 32; r += 8) {
        size_t o = (size_t)(n0 + y + r) * K + k0 + x;
        t[o] = __float2half(ts[x][y + r]);
    }
}

__global__ void dectab_kernel(const float* __restrict__ slopes)
{
    int h = blockIdx.x, i = threadIdx.x;
    float s = slopes[h];
    g_qdectab[h * CC + i] = expf(-s * (float)(i + 1));
    g_kdectab[h * CC + i] = expf(-s * (float)(CC - 1 - i));
}

// g_qkv -> q hi/lo + k single in [bh][s][d] fp16
__global__ __launch_bounds__(256) void splitqkv_norm()
{
    int idx = blockIdx.x * 256 + threadIdx.x;
    int d4 = idx & 31; int rest = idx >> 5;
    int h = rest & 15; rest >>= 4;
    int s = rest & 4095; int b = rest >> 12;

    size_t qo = (size_t)(b * SS + s) * QKVN + h * HD + d4 * 4;
    float4 q = *(const float4*)&g_qkv[qo];
    float4 k = *(const float4*)&g_qkv[qo + HIDN];

    size_t o = ((size_t)(b * NH + h) * SS + s) * HD + d4 * 4;
    split_store4h(g_q_hi, g_q_lo, o, q, 1.0f);
    store4h(g_k, o, k);
}

// g_qkv k,v -> kdT hi/lo + vT single in [bh][d][s] fp16
__global__ void trans_split_head()
{
    __shared__ float tk[32][33], tv[32][33];
    const int z  = blockIdx.z;
    const int b  = z >> 4, h = z & 15;
    const int s0 = blockIdx.x * 32;
    const int d0 = blockIdx.y * 32;
    const int x = threadIdx.x, y = threadIdx.y;

    #pragma unroll
    for (int r = 0; r < 32; r += 8) {
        size_t base = (size_t)(b * SS + s0 + y + r) * QKVN + h * HD + d0 + x;
        tk[y + r][x] = g_qkv[base + HIDN];
        tv[y + r][x] = g_qkv[base + 2 * HIDN];
    }
    __syncthreads();
    #pragma unroll
    for (int r = 0; r < 32; r += 8) {
        int d = d0 + y + r;
        int s = s0 + x;
        float kdec = g_kdectab[h * CC + (s & (CC - 1))];
        float kv = tk[x][y + r] * kdec;
        float vv = tv[x][y + r];
        size_t o = ((size_t)z * HD + d) * SS + s;
        __half h1 = __float2half(kv);
        g_kdT_hi[o] = h1;
        g_kdT_lo[o] = __float2half(kv - __half2float(h1));
        g_vT[o] = __float2half(vv);
    }
}

// g_kvstate [bhn][d'][e] -> kvsT [bhn][e][d'] single fp16
__global__ void kvsplitT_kernel()
{
    __shared__ float t[32][33];
    const int bhn = blockIdx.z;
    const int d0 = blockIdx.x * 32;
    const int e0 = blockIdx.y * 32;
    const int x = threadIdx.x, y = threadIdx.y;
    const size_t base = (size_t)bhn * HD * HD;

    #pragma unroll
    for (int r = 0; r < 32; r += 8)
        t[y + r][x] = g_kvstate[base + (size_t)(d0 + y + r) * HD + e0 + x];
    __syncthreads();
    #pragma unroll
    for (int r = 0; r < 32; r += 8) {
        float v = t[x][y + r];
        size_t o = base + (size_t)(e0 + y + r) * HD + d0 + x;
        g_kvsT[o] = __float2half(v);
    }
}

// ---------------- kvdelta via HMMA (fp16 2-pass, double-buffered) ----------------
// delta[d][e] = sum_j kdT[d][j] * vT[e][j]
#define KD_MAT  18432
#define KD_BUF  (3 * KD_MAT)          // 55296
#define KD_SMEM (2 * KD_BUF)          // 110592

__global__ __launch_bounds__(256) void kvdelta_mma()
{
    extern __shared__ char smraw[];
    const uint32_t sb = smem_u32(smraw);

    const int blk = blockIdx.x;
    const int n  = blk & (NCC - 1);
    const int bh = blk >> 4;
    const size_t colb = (size_t)bh * HD;

    const int tid = threadIdx.x, lane = tid & 31, wid = tid >> 5;
    const int wm = (wid >> 2) * 64;
    const int wn = (wid & 3) * 32;

    auto prefetch = [&](int kt, int buf) {
        const uint32_t bbase = sb + buf * KD_BUF;
        const int k0 = n * CC + kt * 64;
        #pragma unroll
        for (int it = 0; it < 4; ++it) {
            int idx = tid + 256 * it;
            int row = idx >> 3, sec = idx & 7;
            size_t g = (colb + row) * SS + k0 + sec * 8;
            uint32_t so = row * 144 + sec * 16;
            cpasync16(bbase + 0 * KD_MAT + so, g_kdT_hi + g);
            cpasync16(bbase + 1 * KD_MAT + so, g_kdT_lo + g);
            cpasync16(bbase + 2 * KD_MAT + so, g_vT + g);
        }
        cp_commit();
    };

    float acc[4][4][4];
    #pragma unroll
    for (int mi = 0; mi < 4; ++mi)
        #pragma unroll
        for (int ni = 0; ni < 4; ++ni)
            #pragma unroll
            for (int r = 0; r < 4; ++r) acc[mi][ni][r] = 0.0f;

    prefetch(0, 0);

    for (int kt = 0; kt < 4; ++kt) {
        const int cur = kt & 1;
        if (kt + 1 < 4) prefetch(kt + 1, cur ^ 1);
        if (kt + 1 < 4) cp_wait<1>(); else cp_wait<0>();
        __syncthreads();

        const uint32_t bbase = sb + cur * KD_BUF;
        #pragma unroll
        for (int ks = 0; ks < 4; ++ks) {
            uint32_t aH[4][4], aL[4][4], bF[4][2];
            const uint32_t ao = (uint32_t)(lane & 15) * 144 + (lane >> 4) * 16 + ks * 32;
            #pragma unroll
            for (int mi = 0; mi < 4; ++mi) {
                ldm_x4(aH[mi], bbase + 0 * KD_MAT + (wm + mi * 16) * 144 + ao);
                ldm_x4(aL[mi], bbase + 1 * KD_MAT + (wm + mi * 16) * 144 + ao);
            }
            const uint32_t bo = (uint32_t)(lane & 7) * 144 + ((lane >> 3) & 1) * 16 + ks * 32;
            #pragma unroll
            for (int ni = 0; ni < 4; ++ni)
                ldm_x2(bF[ni], bbase + 2 * KD_MAT + (wn + ni * 8) * 144 + bo);
            #pragma unroll
            for (int mi = 0; mi < 4; ++mi)
                #pragma unroll
                for (int ni = 0; ni < 4; ++ni)
                    mma16816h(acc[mi][ni], aH[mi], bF[ni]);
            #pragma unroll
            for (int mi = 0; mi < 4; ++mi)
                #pragma unroll
                for (int ni = 0; ni < 4; ++ni)
                    mma16816h(acc[mi][ni], aL[mi], bF[ni]);
        }
        __syncthreads();
    }

    const int erow = lane >> 2, ecol = 2 * (lane & 3);
    float* out = &g_kvdelta[(size_t)blk * HD * HD];
    #pragma unroll
    for (int mi = 0; mi < 4; ++mi) {
        #pragma unroll
        for (int ni = 0; ni < 4; ++ni) {
            int d = wm + mi * 16 + erow;
            int e = wn + ni * 8 + ecol;
            *(float2*)(out + (size_t)d * HD + e)       = make_float2(acc[mi][ni][0], acc[mi][ni][1]);
            *(float2*)(out + (size_t)(d + 8) * HD + e) = make_float2(acc[mi][ni][2], acc[mi][ni][3]);
        }
    }
}

// ---------------- scan (parallel) ----------------
__global__ __launch_bounds__(256) void scan_kernel(const float* __restrict__ slopes)
{
    const int gid = blockIdx.x * 256 + threadIdx.x;
    const int bh  = gid >> 14;
    const int p   = gid & 16383;
    const float bd = expf(-slopes[bh & (NH - 1)] * (float)CC);
    const size_t base = (size_t)bh * NCC * HD * HD + p;

    float st = 0.0f;
    #pragma unroll
    for (int nn = 0; nn < NCC; nn++) {
        g_kvstate[base + (size_t)nn * HD * HD] = st;
        st = bd * st + g_kvdelta[base + (size_t)nn * HD * HD];
    }
}

// ---------------- fused attention via HMMA (fp16 2-pass, pipelined, inter-first) ----------------
// layout (bytes):
//  q   hi 0       lo 34816   (128 x 272)
//  k   69632                 (64 x 272)
//  vT  buf0 87040  buf1 105472  (128 x 144 each)
//  S   hi 123904  lo 142336  (128 x 144 each)
//  kvsT (inter only) at 105472 (128 x 272 = 34816, spans VT1+SHI; VT0 untouched)
#define A_QHI   0
#define A_QLO   34816
#define A_K     69632
#define A_VT0   87040
#define A_VT1   105472
#define A_SHI   123904
#define A_SLO   142336
#define A_SMEM  160768
#define A_KVS   105472

__global__ __launch_bounds__(256) void attn_mma(const float* __restrict__ slopes)
{
    extern __shared__ char smraw[];
    const uint32_t sb = smem_u32(smraw);
    __shared__ float sdec[CC];

    const int blk = blockIdx.x;
    const int itile = blockIdx.y;
    const int n  = blk & (NCC - 1);
    const int bh = blk >> 4;
    const int h  = bh & (NH - 1);
    const int b  = bh >> 4;
    const float s = slopes[h];

    const int tid = threadIdx.x, lane = tid & 31, wid = tid >> 5;
    sdec[tid] = expf(-s * (float)tid);
    const float fexp = expf(-s);

    const size_t rowb = (size_t)bh * SS + n * CC;
    const size_t colb = (size_t)bh * HD;
    const int i0 = itile * 128;

    // group 0: q hi/lo (2048 sectors each) + kvsT single (2048 sectors)
    #pragma unroll
    for (int it = 0; it < 8; ++it) {
        int idx = tid + 256 * it;
        int row = idx >> 4, sec = idx & 15;
        size_t g = (rowb + i0 + row) * HD + sec * 8;
        uint32_t so = row * 272 + sec * 16;
        cpasync16(sb + A_QHI + so, g_q_hi + g);
        cpasync16(sb + A_QLO + so, g_q_lo + g);
    }
    {
        const size_t kvb = (size_t)blk * HD * HD;
        #pragma unroll
        for (int it = 0; it < 8; ++it) {
            int idx = tid + 256 * it;
            int row = idx >> 4, sec = idx & 15;
            size_t g = kvb + (size_t)row * HD + sec * 8;
            uint32_t so = row * 272 + sec * 16;
            cpasync16(sb + A_KVS + so, g_kvsT + g);
        }
    }
    cp_commit();

    // group 1: vT(j=0) single into buf0 (1024 sectors)
    #pragma unroll
    for (int it = 0; it < 4; ++it) {
        int idx = tid + 256 * it;
        int row = idx >> 3, sec = idx & 7;
        size_t g = (colb + row) * SS + n * CC + sec * 8;
        uint32_t so = row * 144 + sec * 16;
        cpasync16(sb + A_VT0 + so, g_vT + g);
    }
    cp_commit();

    const int wm  = (wid >> 2) * 64;
    const int wns = (wid & 3) * 16;
    const int wno = (wid & 3) * 32;
    const int erow = lane >> 2, ecol = 2 * (lane & 3);

    float oacc[4][4][4];
    #pragma unroll
    for (int mi = 0; mi < 4; ++mi)
        #pragma unroll
        for (int ni = 0; ni < 4; ++ni)
            #pragma unroll
            for (int r = 0; r < 4; ++r) oacc[mi][ni][r] = 0.0f;

    // ---- inter FIRST: oacc = q @ kvsT, then row-scale by qdec ----
    cp_wait<1>();
    __syncthreads();

    #pragma unroll
    for (int ks = 0; ks < 8; ++ks) {
        uint32_t aH[4][4], aL[4][4], bF[4][2];
        const uint32_t ao = (uint32_t)(lane & 15) * 272 + (lane >> 4) * 16 + ks * 32;
        #pragma unroll
        for (int mi = 0; mi < 4; ++mi) {
            ldm_x4(aH[mi], sb + A_QHI + (wm + mi * 16) * 272 + ao);
            ldm_x4(aL[mi], sb + A_QLO + (wm + mi * 16) * 272 + ao);
        }
        const uint32_t bo = (uint32_t)(lane & 7) * 272 + ((lane >> 3) & 1) * 16 + ks * 32;
        #pragma unroll
        for (int ni = 0; ni < 4; ++ni)
            ldm_x2(bF[ni], sb + A_KVS + (wno + ni * 8) * 272 + bo);
        #pragma unroll
        for (int mi = 0; mi < 4; ++mi)
            #pragma unroll
            for (int ni = 0; ni < 4; ++ni)
                mma16816h(oacc[mi][ni], aH[mi], bF[ni]);
        #pragma unroll
        for (int mi = 0; mi < 4; ++mi)
            #pragma unroll
            for (int ni = 0; ni < 4; ++ni)
                mma16816h(oacc[mi][ni], aL[mi], bF[ni]);
    }
    #pragma unroll
    for (int mi = 0; mi < 4; ++mi) {
        const int il0 = wm + mi * 16 + erow;
        const float qd0 = sdec[i0 + il0] * fexp;
        const float qd1 = sdec[i0 + il0 + 8] * fexp;
        #pragma unroll
        for (int ni = 0; ni < 4; ++ni) {
            oacc[mi][ni][0] *= qd0;
            oacc[mi][ni][1] *= qd0;
            oacc[mi][ni][2] *= qd1;
            oacc[mi][ni][3] *= qd1;
        }
    }
    __syncthreads();   // all warps done reading kvsT before k(0)/S overwrite its span

    // load k(0) (1024 sectors)
    #pragma unroll
    for (int it = 0; it < 4; ++it) {
        int idx = tid + 256 * it;
        int row = idx >> 4, sec = idx & 15;
        size_t g = (rowb + row) * HD + sec * 8;
        uint32_t so = row * 272 + sec * 16;
        cpasync16(sb + A_K + so, g_k + g);
    }
    cp_commit();

    const int njt = 2 * (itile + 1);
    for (int jt = 0; jt < njt; ++jt) {
        const int j0 = jt * 64;
        const int cur = jt & 1;
        const uint32_t vtb = sb + (cur ? A_VT1 : A_VT0);

        cp_wait<0>();
        __syncthreads();

        // ---- S = q @ k^T (2-pass) ----
        float sacc[4][2][4];
        #pragma unroll
        for (int mi = 0; mi < 4; ++mi)
            #pragma unroll
            for (int ni = 0; ni < 2; ++ni)
                #pragma unroll
                for (int r = 0; r < 4; ++r) sacc[mi][ni][r] = 0.0f;

        #pragma unroll
        for (int ks = 0; ks < 8; ++ks) {
            uint32_t aH[4][4], aL[4][4], bF[2][2];
            const uint32_t ao = (uint32_t)(lane & 15) * 272 + (lane >> 4) * 16 + ks * 32;
            #pragma unroll
            for (int mi = 0; mi < 4; ++mi) {
                ldm_x4(aH[mi], sb + A_QHI + (wm + mi * 16) * 272 + ao);
                ldm_x4(aL[mi], sb + A_QLO + (wm + mi * 16) * 272 + ao);
            }
            const uint32_t bo = (uint32_t)(lane & 7) * 272 + ((lane >> 3) & 1) * 16 + ks * 32;
            #pragma unroll
            for (int ni = 0; ni < 2; ++ni)
                ldm_x2(bF[ni], sb + A_K + (wns + ni * 8) * 272 + bo);
            #pragma unroll
            for (int mi = 0; mi < 4; ++mi)
                #pragma unroll
                for (int ni = 0; ni < 2; ++ni)
                    mma16816h(sacc[mi][ni], aH[mi], bF[ni]);
            #pragma unroll
            for (int mi = 0; mi < 4; ++mi)
                #pragma unroll
                for (int ni = 0; ni < 2; ++ni)
                    mma16816h(sacc[mi][ni], aL[mi], bF[ni]);
        }

        // ---- decay + split S (fp16 hi/lo) ----
        #pragma unroll
        for (int mi = 0; mi < 4; ++mi) {
            #pragma unroll
            for (int ni = 0; ni < 2; ++ni) {
                #pragma unroll
                for (int r = 0; r < 4; ++r) {
                    int il = wm + mi * 16 + erow + (r >> 1) * 8;
                    int jl = wns + ni * 8 + ecol + (r & 1);
                    int dd = (i0 + il) - (j0 + jl);
                    float val = (dd >= 0) ? sacc[mi][ni][r] * sdec[dd] : 0.0f;
                    __half hi = __float2half(val);
                    __half lo = __float2half(val - __half2float(hi));
                    *(__half*)(smraw + A_SHI + il * 144 + jl * 2) = hi;
                    *(__half*)(smraw + A_SLO + il * 144 + jl * 2) = lo;
                }
            }
        }
        __syncthreads();   // S visible; k buffer free

        // prefetch k(jt+1) and vT(jt+1)
        if (jt + 1 < njt) {
            const int jn = (jt + 1) * 64;
            #pragma unroll
            for (int it = 0; it < 4; ++it) {
                int idx = tid + 256 * it;
                int row = idx >> 4, sec = idx & 15;
                size_t g = (rowb + jn + row) * HD + sec * 8;
                uint32_t so = row * 272 + sec * 16;
                cpasync16(sb + A_K + so, g_k + g);
            }
            const uint32_t vtn = sb + (cur ? A_VT0 : A_VT1);
            #pragma unroll
            for (int it = 0; it < 4; ++it) {
                int idx = tid + 256 * it;
                int row = idx >> 3, sec = idx & 7;
                size_t g = (colb + row) * SS + n * CC + jn + sec * 8;
                uint32_t so = row * 144 + sec * 16;
                cpasync16(vtn + so, g_vT + g);
            }
            cp_commit();
        }

        // ---- O += S̃ @ v (2-pass) ----
        #pragma unroll
        for (int ks = 0; ks < 4; ++ks) {
            uint32_t aH[4][4], aL[4][4], bF[4][2];
            const uint32_t ao = (uint32_t)(lane & 15) * 144 + (lane >> 4) * 16 + ks * 32;
            #pragma unroll
            for (int mi = 0; mi < 4; ++mi) {
                ldm_x4(aH[mi], sb + A_SHI + (wm + mi * 16) * 144 + ao);
                ldm_x4(aL[mi], sb + A_SLO + (wm + mi * 16) * 144 + ao);
            }
            const uint32_t bo = (uint32_t)(lane & 7) * 144 + ((lane >> 3) & 1) * 16 + ks * 32;
            #pragma unroll
            for (int ni = 0; ni < 4; ++ni)
                ldm_x2(bF[ni], vtb + (wno + ni * 8) * 144 + bo);
            #pragma unroll
            for (int mi = 0; mi < 4; ++mi)
                #pragma unroll
                for (int ni = 0; ni < 4; ++ni)
                    mma16816h(oacc[mi][ni], aH[mi], bF[ni]);
            #pragma unroll
            for (int mi = 0; mi < 4; ++mi)
                #pragma unroll
                for (int ni = 0; ni < 4; ++ni)
                    mma16816h(oacc[mi][ni], aL[mi], bF[ni]);
        }
    }

    // ---- epilogue: gate-fused fp16 split store ----
    #pragma unroll
    for (int mi = 0; mi < 4; ++mi) {
        #pragma unroll
        for (int ni = 0; ni < 4; ++ni) {
            int il = wm + mi * 16 + erow;
            int e  = wno + ni * 8 + ecol;
            size_t o0 = (size_t)(b * SS + n * CC + i0 + il) * HIDN + h * HD + e;
            size_t o1 = o0 + 8 * HIDN;
            float2 g0 = *(const float2*)(g_gate + o0);
            float2 g1 = *(const float2*)(g_gate + o1);
            float v0 = oacc[mi][ni][0] * g0.x;
            float v1 = oacc[mi][ni][1] * g0.y;
            float v2 = oacc[mi][ni][2] * g1.x;
            float v3 = oacc[mi][ni][3] * g1.y;
            __half h0 = __float2half(v0), h1b = __float2half(v1);
            __half h2 = __float2half(v2), h3b = __float2half(v3);
            *(__half2*)(g_gah + o0) = __halves2half2(h0, h1b);
            *(__half2*)(g_gah + o1) = __halves2half2(h2, h3b);
            *(__half2*)(g_gal + o0) = __halves2half2(
                __float2half(v0 - __half2float(h0)),
                __float2half(v1 - __half2float(h1b)));
            *(__half2*)(g_gal + o1) = __halves2half2(
                __float2half(v2 - __half2float(h2)),
                __float2half(v3 - __half2float(h3b)));
        }
    }
}

// ---------------- launch ----------------
extern "C" void kernel_launch(void* const* d_in, const int* in_sizes, int n_in,
                              void* d_out, int out_size)
{
    const float* x      = (const float*)d_in[0];
    const float* w_qkv  = (const float*)d_in[1];
    const float* w_gate = (const float*)d_in[2];
    const float* w_out  = (const float*)d_in[3];
    const float* slopes = (const float*)d_in[4];
    float* out = (float*)d_out;

    float *qkv_p, *gate_p;
    cudaGetSymbolAddress((void**)&qkv_p,  g_qkv);
    cudaGetSymbolAddress((void**)&gate_p, g_gate);

    __half *xh, *xl, *wqh, *wgh, *woh, *gah, *gal;
    cudaGetSymbolAddress((void**)&xh,  g_xh);
    cudaGetSymbolAddress((void**)&xl,  g_xl);
    cudaGetSymbolAddress((void**)&wqh, g_wqkvT_h);
    cudaGetSymbolAddress((void**)&wgh, g_wgateT_h);
    cudaGetSymbolAddress((void**)&woh, g_woutT_h);
    cudaGetSymbolAddress((void**)&gah, g_gah);
    cudaGetSymbolAddress((void**)&gal, g_gal);

    cudaFuncSetAttribute(mma_gemm_h<EPI_SILU>,
                         cudaFuncAttributeMaxDynamicSharedMemorySize, GEMMH_SMEM);
    cudaFuncSetAttribute(mma_gemm_h<EPI_SIGMOID>,
                         cudaFuncAttributeMaxDynamicSharedMemorySize, GEMMH_SMEM);
    cudaFuncSetAttribute(mma_gemm_h<EPI_NONE>,
                         cudaFuncAttributeMaxDynamicSharedMemorySize, GEMMH_SMEM);
    cudaFuncSetAttribute(attn_mma,
                         cudaFuncAttributeMaxDynamicSharedMemorySize, A_SMEM);
    cudaFuncSetAttribute(kvdelta_mma,
                         cudaFuncAttributeMaxDynamicSharedMemorySize, KD_SMEM);

    // 0) splits + transposes + decay tables
    {
        int n4 = MM * HIDN / 4;
        splith_kernel<<<n4 / 256, 256>>>(x, xh, xl, n4);
        dim3 blk(32, 8);
        transp_half_kernel<<<dim3(QKVN / 32, HIDN / 32), blk>>>(w_qkv,  wqh, HIDN, QKVN);
        transp_half_kernel<<<dim3(HIDN / 32, HIDN / 32), blk>>>(w_gate, wgh, HIDN, HIDN);
        transp_half_kernel<<<dim3(HIDN / 32, HIDN / 32), blk>>>(w_out,  woh, HIDN, HIDN);
        dectab_kernel<<<NH, CC>>>(slopes);
    }
    // 1) qkv = silu(x @ w_qkv)
    mma_gemm_h<EPI_SILU><<<dim3(QKVN / 256, MM / 128), 512, GEMMH_SMEM>>>(
        xh, xl, wqh, qkv_p, MM, QKVN);
    // 2) per-head splits
    splitqkv_norm<<<(BB * SS * NH * 32) / 256, 256>>>();
    {
        dim3 blk(32, 8);
        trans_split_head<<<dim3(SS / 32, HD / 32, BB * NH), blk>>>();
    }
    // 3) gate = sigmoid(x @ w_gate)
    mma_gemm_h<EPI_SIGMOID><<<dim3(HIDN / 256, MM / 128), 512, GEMMH_SMEM>>>(
        xh, xl, wgh, gate_p, MM, HIDN);
    // 4) attention pipeline (fp16 2-pass)
    kvdelta_mma<<<BB * NH * NCC, 256, KD_SMEM>>>();
    scan_kernel<<<BB * NH * 64, 256>>>(slopes);
    {
        dim3 blk(32, 8);
        kvsplitT_kernel<<<dim3(HD / 32, HD / 32, BB * NH * NCC), blk>>>();
    }
    attn_mma<<<dim3(BB * NH * NCC, 2), 256, A_SMEM>>>(slopes);
    // 5) out = (gate*attn) @ w_out   [fp16 2-pass]
    mma_gemm_h<EPI_NONE><<<dim3(HIDN / 256, MM / 128), 512, GEMMH_SMEM>>>(
        gah, gal, woh, out, MM, HIDN);
}

// round 11
// speedup vs baseline: 2.2719x; 1.6039x over previous
#include <cuda_runtime.h>
#include <cuda_fp16.h>
#include <math.h>
#include <stdint.h>

// ---------------- problem constants ----------------
#define BB   2
#define SS   4096
#define HIDN 2048
#define NH   16
#define HD   128
#define CC   256
#define NCC  16
#define MM   (BB*SS)          // 8192
#define QKVN (3*HIDN)         // 6144
#define GK   HIDN
#define BKC  64
#define NCHUNK (GK/BKC)       // 32

// ---------------- device scratch ----------------
__device__ float g_qkv   [(size_t)MM * QKVN];
__device__ float g_gate  [(size_t)MM * HIDN];
__device__ float g_kvdelta[(size_t)BB*NH*NCC*HD*HD];
__device__ float g_kvstate[(size_t)BB*NH*NCC*HD*HD];

// fp16 1-pass operands
__device__ __half g_x16[(size_t)MM*HIDN];
__device__ __half g_wqkvT_h[(size_t)QKVN*HIDN];
__device__ __half g_wgateT_h[(size_t)HIDN*HIDN];
__device__ __half g_woutT_h[(size_t)HIDN*HIDN];
__device__ __half g_ga16[(size_t)MM*HIDN];

#define PHSZ ((size_t)BB*NH*SS*HD)
__device__ __half g_q16 [PHSZ];                    // [bh][s][d]
__device__ __half g_k16 [PHSZ];                    // [bh][s][d]
__device__ __half g_kdT [PHSZ];                    // [bh][d][s]
__device__ __half g_vT  [PHSZ];                    // [bh][d][s]
__device__ __half g_kvsT[(size_t)BB*NH*NCC*HD*HD]; // [bhn][e][d']
__device__ float g_qdectab[NH*CC], g_kdectab[NH*CC];

// ---------------- epilogues ----------------
#define EPI_SILU    0
#define EPI_SIGMOID 1
#define EPI_NONE    2

__device__ __forceinline__ float apply_epi(float x, int mode) {
    if (mode == EPI_SILU)    return x / (1.0f + expf(-x));
    if (mode == EPI_SIGMOID) return 1.0f / (1.0f + expf(-x));
    return x;
}

// ---------------- base-ISA tensor-core helpers ----------------
__device__ __forceinline__ uint32_t smem_u32(const void* p) {
    uint32_t a;
    asm("{ .reg .u64 t; cvta.to.shared.u64 t, %1; cvt.u32.u64 %0, t; }" : "=r"(a) : "l"(p));
    return a;
}
__device__ __forceinline__ void cpasync16(uint32_t saddr, const void* g) {
    asm volatile("cp.async.cg.shared.global [%0], [%1], 16;" :: "r"(saddr), "l"(g));
}
__device__ __forceinline__ void cp_commit() {
    asm volatile("cp.async.commit_group;" ::: "memory");
}
template<int N> __device__ __forceinline__ void cp_wait() {
    asm volatile("cp.async.wait_group %0;" :: "n"(N) : "memory");
}
__device__ __forceinline__ void ldm_x4(uint32_t* r, uint32_t addr) {
    asm volatile("ldmatrix.sync.aligned.m8n8.x4.shared.b16 {%0,%1,%2,%3}, [%4];"
                 : "=r"(r[0]), "=r"(r[1]), "=r"(r[2]), "=r"(r[3]) : "r"(addr));
}
__device__ __forceinline__ void ldm_x2(uint32_t* r, uint32_t addr) {
    asm volatile("ldmatrix.sync.aligned.m8n8.x2.shared.b16 {%0,%1}, [%2];"
                 : "=r"(r[0]), "=r"(r[1]) : "r"(addr));
}
__device__ __forceinline__ void mma16816h(float* c, const uint32_t* a, const uint32_t* b) {
    asm volatile(
        "mma.sync.aligned.m16n8k16.row.col.f32.f16.f16.f32 "
        "{%0,%1,%2,%3},{%4,%5,%6,%7},{%8,%9},{%0,%1,%2,%3};"
        : "+f"(c[0]), "+f"(c[1]), "+f"(c[2]), "+f"(c[3])
        : "r"(a[0]), "r"(a[1]), "r"(a[2]), "r"(a[3]), "r"(b[0]), "r"(b[1]));
}

#define LDSW   144

// ---------------- fp16 1-pass GEMM: C = A @ B^T, tile 128x256, 512 thr ----------------
#define HA_SZ  (128 * LDSW)               // 18432
#define HB_SZ  (256 * LDSW)               // 36864
#define H1BUF  (HA_SZ + HB_SZ)            // 55296
#define GEMM1_SMEM (2 * H1BUF)            // 110592

template<int EPI>
__global__ __launch_bounds__(512) void mma_gemm_1(
    const __half* __restrict__ A, const __half* __restrict__ Bh,
    float* __restrict__ C, int M, int N)
{
    extern __shared__ char smraw[];
    const uint32_t sb = smem_u32(smraw);

    const int tid  = threadIdx.x;
    const int lane = tid & 31;
    const int wid  = tid >> 5;
    const int bm = blockIdx.y * 128;
    const int bn = blockIdx.x * 256;
    const int wm = (wid >> 3) * 64;
    const int wn = (wid & 7) * 32;

    auto prefetch = [&](int c, int buf) {
        const uint32_t bbase = sb + buf * H1BUF;
        const int k0 = c * BKC;
        #pragma unroll
        for (int i = 0; i < 2; ++i) {
            int idx = tid + 512 * i;
            int row = idx >> 3, sec = idx & 7;
            const uint32_t so = row * LDSW + sec * 16;
            const size_t ga = (size_t)(bm + row) * GK + k0 + sec * 8;
            cpasync16(bbase + so, A + ga);
        }
        #pragma unroll
        for (int i = 0; i < 4; ++i) {
            int idx = tid + 512 * i;
            int row = idx >> 3, sec = idx & 7;
            const uint32_t so = row * LDSW + sec * 16;
            const size_t gb = (size_t)(bn + row) * GK + k0 + sec * 8;
            cpasync16(bbase + HA_SZ + so, Bh + gb);
        }
        cp_commit();
    };

    float acc[4][4][4];
    #pragma unroll
    for (int mi = 0; mi < 4; ++mi)
        #pragma unroll
        for (int ni = 0; ni < 4; ++ni)
            #pragma unroll
            for (int r = 0; r < 4; ++r) acc[mi][ni][r] = 0.0f;

    const uint32_t aOff = (uint32_t)(wm + (lane & 15)) * LDSW + (lane >> 4) * 16;
    const uint32_t bOff = (uint32_t)(wn + (lane & 7))  * LDSW + ((lane >> 3) & 1) * 16;

    prefetch(0, 0);

    for (int c = 0; c < NCHUNK; ++c) {
        const int cur = c & 1;
        if (c + 1 < NCHUNK) prefetch(c + 1, cur ^ 1);
        if (c + 1 < NCHUNK) cp_wait<1>(); else cp_wait<0>();
        __syncthreads();

        const uint32_t bbase = sb + cur * H1BUF;
        #pragma unroll
        for (int ks = 0; ks < 4; ++ks) {
            const uint32_t kso = ks * 32;
            uint32_t aF[4][4], bF[4][2];
            #pragma unroll
            for (int mi = 0; mi < 4; ++mi)
                ldm_x4(aF[mi], bbase + aOff + mi * 16 * LDSW + kso);
            #pragma unroll
            for (int ni = 0; ni < 4; ++ni)
                ldm_x2(bF[ni], bbase + HA_SZ + bOff + ni * 8 * LDSW + kso);
            #pragma unroll
            for (int mi = 0; mi < 4; ++mi)
                #pragma unroll
                for (int ni = 0; ni < 4; ++ni)
                    mma16816h(acc[mi][ni], aF[mi], bF[ni]);
        }
        __syncthreads();
    }

    const int erow = lane >> 2;
    const int ecol = 2 * (lane & 3);
    #pragma unroll
    for (int mi = 0; mi < 4; ++mi) {
        #pragma unroll
        for (int ni = 0; ni < 4; ++ni) {
            const int gr0 = bm + wm + mi * 16 + erow;
            const int gc  = bn + wn + ni * 8 + ecol;
            float2 v0, v1;
            v0.x = apply_epi(acc[mi][ni][0], EPI);
            v0.y = apply_epi(acc[mi][ni][1], EPI);
            v1.x = apply_epi(acc[mi][ni][2], EPI);
            v1.y = apply_epi(acc[mi][ni][3], EPI);
            *(float2*)(C + (size_t)gr0 * N + gc)       = v0;
            *(float2*)(C + (size_t)(gr0 + 8) * N + gc) = v1;
        }
    }
}

// ---------------- conversion kernels ----------------
__device__ __forceinline__ void store4h(__half* d, size_t o, float4 v)
{
    *(__half2*)(d + o)     = __halves2half2(__float2half(v.x), __float2half(v.y));
    *(__half2*)(d + o + 2) = __halves2half2(__float2half(v.z), __float2half(v.w));
}

// x fp32 -> fp16
__global__ __launch_bounds__(256) void tohalf_kernel(
    const float* __restrict__ in, __half* __restrict__ d16, int n4)
{
    int i = blockIdx.x * 256 + threadIdx.x;
    if (i >= n4) return;
    store4h(d16, (size_t)i * 4, ((const float4*)in)[i]);
}

// w [K,N] fp32 -> wT [N,K] fp16
__global__ void transp_half_kernel(
    const float* __restrict__ w, __half* __restrict__ t, int K, int N)
{
    __shared__ float ts[32][33];
    const int n0 = blockIdx.x * 32, k0 = blockIdx.y * 32;
    const int x = threadIdx.x, y = threadIdx.y;
    #pragma unroll
    for (int r = 0; r < 32; r += 8)
        ts[y + r][x] = w[(size_t)(k0 + y + r) * N + n0 + x];
    __syncthreads();
    #pragma unroll
    for (int r = 0; r < 32; r += 8) {
        size_t o = (size_t)(n0 + y + r) * K + k0 + x;
        t[o] = __float2half(ts[x][y + r]);
    }
}

__global__ void dectab_kernel(const float* __restrict__ slopes)
{
    int h = blockIdx.x, i = threadIdx.x;
    float s = slopes[h];
    g_qdectab[h * CC + i] = expf(-s * (float)(i + 1));
    g_kdectab[h * CC + i] = expf(-s * (float)(CC - 1 - i));
}

// g_qkv -> q, k in [bh][s][d] fp16
__global__ __launch_bounds__(256) void splitqkv_norm()
{
    int idx = blockIdx.x * 256 + threadIdx.x;
    int d4 = idx & 31; int rest = idx >> 5;
    int h = rest & 15; rest >>= 4;
    int s = rest & 4095; int b = rest >> 12;

    size_t qo = (size_t)(b * SS + s) * QKVN + h * HD + d4 * 4;
    float4 q = *(const float4*)&g_qkv[qo];
    float4 k = *(const float4*)&g_qkv[qo + HIDN];

    size_t o = ((size_t)(b * NH + h) * SS + s) * HD + d4 * 4;
    store4h(g_q16, o, q);
    store4h(g_k16, o, k);
}

// g_qkv k,v -> kdT, vT in [bh][d][s] fp16
__global__ void trans_split_head()
{
    __shared__ float tk[32][33], tv[32][33];
    const int z  = blockIdx.z;
    const int b  = z >> 4, h = z & 15;
    const int s0 = blockIdx.x * 32;
    const int d0 = blockIdx.y * 32;
    const int x = threadIdx.x, y = threadIdx.y;

    #pragma unroll
    for (int r = 0; r < 32; r += 8) {
        size_t base = (size_t)(b * SS + s0 + y + r) * QKVN + h * HD + d0 + x;
        tk[y + r][x] = g_qkv[base + HIDN];
        tv[y + r][x] = g_qkv[base + 2 * HIDN];
    }
    __syncthreads();
    #pragma unroll
    for (int r = 0; r < 32; r += 8) {
        int d = d0 + y + r;
        int s = s0 + x;
        float kdec = g_kdectab[h * CC + (s & (CC - 1))];
        size_t o = ((size_t)z * HD + d) * SS + s;
        g_kdT[o] = __float2half(tk[x][y + r] * kdec);
        g_vT[o]  = __float2half(tv[x][y + r]);
    }
}

// g_kvstate [bhn][d'][e] -> kvsT [bhn][e][d'] fp16
__global__ void kvsplitT_kernel()
{
    __shared__ float t[32][33];
    const int bhn = blockIdx.z;
    const int d0 = blockIdx.x * 32;
    const int e0 = blockIdx.y * 32;
    const int x = threadIdx.x, y = threadIdx.y;
    const size_t base = (size_t)bhn * HD * HD;

    #pragma unroll
    for (int r = 0; r < 32; r += 8)
        t[y + r][x] = g_kvstate[base + (size_t)(d0 + y + r) * HD + e0 + x];
    __syncthreads();
    #pragma unroll
    for (int r = 0; r < 32; r += 8) {
        size_t o = base + (size_t)(e0 + y + r) * HD + d0 + x;
        g_kvsT[o] = __float2half(t[x][y + r]);
    }
}

// ---------------- kvdelta via HMMA (fp16 1-pass, double-buffered) ----------------
#define KD_MAT  18432
#define KD_BUF  (2 * KD_MAT)          // 36864
#define KD_SMEM (2 * KD_BUF)          // 73728

__global__ __launch_bounds__(256) void kvdelta_mma()
{
    extern __shared__ char smraw[];
    const uint32_t sb = smem_u32(smraw);

    const int blk = blockIdx.x;
    const int n  = blk & (NCC - 1);
    const int bh = blk >> 4;
    const size_t colb = (size_t)bh * HD;

    const int tid = threadIdx.x, lane = tid & 31, wid = tid >> 5;
    const int wm = (wid >> 2) * 64;
    const int wn = (wid & 3) * 32;

    auto prefetch = [&](int kt, int buf) {
        const uint32_t bbase = sb + buf * KD_BUF;
        const int k0 = n * CC + kt * 64;
        #pragma unroll
        for (int it = 0; it < 4; ++it) {
            int idx = tid + 256 * it;
            int row = idx >> 3, sec = idx & 7;
            size_t g = (colb + row) * SS + k0 + sec * 8;
            uint32_t so = row * 144 + sec * 16;
            cpasync16(bbase + 0 * KD_MAT + so, g_kdT + g);
            cpasync16(bbase + 1 * KD_MAT + so, g_vT + g);
        }
        cp_commit();
    };

    float acc[4][4][4];
    #pragma unroll
    for (int mi = 0; mi < 4; ++mi)
        #pragma unroll
        for (int ni = 0; ni < 4; ++ni)
            #pragma unroll
            for (int r = 0; r < 4; ++r) acc[mi][ni][r] = 0.0f;

    prefetch(0, 0);

    for (int kt = 0; kt < 4; ++kt) {
        const int cur = kt & 1;
        if (kt + 1 < 4) prefetch(kt + 1, cur ^ 1);
        if (kt + 1 < 4) cp_wait<1>(); else cp_wait<0>();
        __syncthreads();

        const uint32_t bbase = sb + cur * KD_BUF;
        #pragma unroll
        for (int ks = 0; ks < 4; ++ks) {
            uint32_t aF[4][4], bF[4][2];
            const uint32_t ao = (uint32_t)(lane & 15) * 144 + (lane >> 4) * 16 + ks * 32;
            #pragma unroll
            for (int mi = 0; mi < 4; ++mi)
                ldm_x4(aF[mi], bbase + 0 * KD_MAT + (wm + mi * 16) * 144 + ao);
            const uint32_t bo = (uint32_t)(lane & 7) * 144 + ((lane >> 3) & 1) * 16 + ks * 32;
            #pragma unroll
            for (int ni = 0; ni < 4; ++ni)
                ldm_x2(bF[ni], bbase + 1 * KD_MAT + (wn + ni * 8) * 144 + bo);
            #pragma unroll
            for (int mi = 0; mi < 4; ++mi)
                #pragma unroll
                for (int ni = 0; ni < 4; ++ni)
                    mma16816h(acc[mi][ni], aF[mi], bF[ni]);
        }
        __syncthreads();
    }

    const int erow = lane >> 2, ecol = 2 * (lane & 3);
    float* out = &g_kvdelta[(size_t)blk * HD * HD];
    #pragma unroll
    for (int mi = 0; mi < 4; ++mi) {
        #pragma unroll
        for (int ni = 0; ni < 4; ++ni) {
            int d = wm + mi * 16 + erow;
            int e = wn + ni * 8 + ecol;
            *(float2*)(out + (size_t)d * HD + e)       = make_float2(acc[mi][ni][0], acc[mi][ni][1]);
            *(float2*)(out + (size_t)(d + 8) * HD + e) = make_float2(acc[mi][ni][2], acc[mi][ni][3]);
        }
    }
}

// ---------------- scan (parallel) ----------------
__global__ __launch_bounds__(256) void scan_kernel(const float* __restrict__ slopes)
{
    const int gid = blockIdx.x * 256 + threadIdx.x;
    const int bh  = gid >> 14;
    const int p   = gid & 16383;
    const float bd = expf(-slopes[bh & (NH - 1)] * (float)CC);
    const size_t base = (size_t)bh * NCC * HD * HD + p;

    float st = 0.0f;
    #pragma unroll
    for (int nn = 0; nn < NCC; nn++) {
        g_kvstate[base + (size_t)nn * HD * HD] = st;
        st = bd * st + g_kvdelta[base + (size_t)nn * HD * HD];
    }
}

// ---------------- fused attention via HMMA (fp16 1-pass, pipelined, inter-first) ----------------
// layout (bytes):
//  q   0      (128 x 272 = 34816)
//  k   34816  (64 x 272  = 17408)
//  vT  buf0 52224  buf1 70656   (128 x 144 = 18432 each)
//  S   89088  (128 x 144 = 18432)
//  kvsT (inter only) at 70656 (128 x 272 = 34816; spans VT1+S: 70656..105472 <= 107520; VT0 untouched)
#define A_Q     0
#define A_K     34816
#define A_VT0   52224
#define A_VT1   70656
#define A_S     89088
#define A_SMEM  107520
#define A_KVS   70656

__global__ __launch_bounds__(256) void attn_mma(const float* __restrict__ slopes)
{
    extern __shared__ char smraw[];
    const uint32_t sb = smem_u32(smraw);
    __shared__ float sdec[CC];

    const int blk = blockIdx.x;
    const int itile = blockIdx.y;
    const int n  = blk & (NCC - 1);
    const int bh = blk >> 4;
    const int h  = bh & (NH - 1);
    const int b  = bh >> 4;
    const float s = slopes[h];

    const int tid = threadIdx.x, lane = tid & 31, wid = tid >> 5;
    sdec[tid] = expf(-s * (float)tid);
    const float fexp = expf(-s);

    const size_t rowb = (size_t)bh * SS + n * CC;
    const size_t colb = (size_t)bh * HD;
    const int i0 = itile * 128;

    // group 0: q (2048 sectors) + kvsT (2048 sectors)
    #pragma unroll
    for (int it = 0; it < 8; ++it) {
        int idx = tid + 256 * it;
        int row = idx >> 4, sec = idx & 15;
        size_t g = (rowb + i0 + row) * HD + sec * 8;
        uint32_t so = row * 272 + sec * 16;
        cpasync16(sb + A_Q + so, g_q16 + g);
    }
    {
        const size_t kvb = (size_t)blk * HD * HD;
        #pragma unroll
        for (int it = 0; it < 8; ++it) {
            int idx = tid + 256 * it;
            int row = idx >> 4, sec = idx & 15;
            size_t g = kvb + (size_t)row * HD + sec * 8;
            uint32_t so = row * 272 + sec * 16;
            cpasync16(sb + A_KVS + so, g_kvsT + g);
        }
    }
    cp_commit();

    // group 1: vT(j=0) into buf0 (1024 sectors)
    #pragma unroll
    for (int it = 0; it < 4; ++it) {
        int idx = tid + 256 * it;
        int row = idx >> 3, sec = idx & 7;
        size_t g = (colb + row) * SS + n * CC + sec * 8;
        uint32_t so = row * 144 + sec * 16;
        cpasync16(sb + A_VT0 + so, g_vT + g);
    }
    cp_commit();

    const int wm  = (wid >> 2) * 64;
    const int wns = (wid & 3) * 16;
    const int wno = (wid & 3) * 32;
    const int erow = lane >> 2, ecol = 2 * (lane & 3);

    float oacc[4][4][4];
    #pragma unroll
    for (int mi = 0; mi < 4; ++mi)
        #pragma unroll
        for (int ni = 0; ni < 4; ++ni)
            #pragma unroll
            for (int r = 0; r < 4; ++r) oacc[mi][ni][r] = 0.0f;

    // ---- inter FIRST: oacc = q @ kvsT, then row-scale by qdec ----
    cp_wait<1>();
    __syncthreads();

    #pragma unroll
    for (int ks = 0; ks < 8; ++ks) {
        uint32_t aF[4][4], bF[4][2];
        const uint32_t ao = (uint32_t)(lane & 15) * 272 + (lane >> 4) * 16 + ks * 32;
        #pragma unroll
        for (int mi = 0; mi < 4; ++mi)
            ldm_x4(aF[mi], sb + A_Q + (wm + mi * 16) * 272 + ao);
        const uint32_t bo = (uint32_t)(lane & 7) * 272 + ((lane >> 3) & 1) * 16 + ks * 32;
        #pragma unroll
        for (int ni = 0; ni < 4; ++ni)
            ldm_x2(bF[ni], sb + A_KVS + (wno + ni * 8) * 272 + bo);
        #pragma unroll
        for (int mi = 0; mi < 4; ++mi)
            #pragma unroll
            for (int ni = 0; ni < 4; ++ni)
                mma16816h(oacc[mi][ni], aF[mi], bF[ni]);
    }
    #pragma unroll
    for (int mi = 0; mi < 4; ++mi) {
        const int il0 = wm + mi * 16 + erow;
        const float qd0 = sdec[i0 + il0] * fexp;
        const float qd1 = sdec[i0 + il0 + 8] * fexp;
        #pragma unroll
        for (int ni = 0; ni < 4; ++ni) {
            oacc[mi][ni][0] *= qd0;
            oacc[mi][ni][1] *= qd0;
            oacc[mi][ni][2] *= qd1;
            oacc[mi][ni][3] *= qd1;
        }
    }
    __syncthreads();   // all warps done with kvsT before k(0)/S reuse its span

    // load k(0) (1024 sectors)
    #pragma unroll
    for (int it = 0; it < 4; ++it) {
        int idx = tid + 256 * it;
        int row = idx >> 4, sec = idx & 15;
        size_t g = (rowb + row) * HD + sec * 8;
        uint32_t so = row * 272 + sec * 16;
        cpasync16(sb + A_K + so, g_k16 + g);
    }
    cp_commit();

    const int njt = 2 * (itile + 1);
    for (int jt = 0; jt < njt; ++jt) {
        const int j0 = jt * 64;
        const int cur = jt & 1;
        const uint32_t vtb = sb + (cur ? A_VT1 : A_VT0);

        cp_wait<0>();
        __syncthreads();

        // ---- S = q @ k^T (1-pass) ----
        float sacc[4][2][4];
        #pragma unroll
        for (int mi = 0; mi < 4; ++mi)
            #pragma unroll
            for (int ni = 0; ni < 2; ++ni)
                #pragma unroll
                for (int r = 0; r < 4; ++r) sacc[mi][ni][r] = 0.0f;

        #pragma unroll
        for (int ks = 0; ks < 8; ++ks) {
            uint32_t aF[4][4], bF[2][2];
            const uint32_t ao = (uint32_t)(lane & 15) * 272 + (lane >> 4) * 16 + ks * 32;
            #pragma unroll
            for (int mi = 0; mi < 4; ++mi)
                ldm_x4(aF[mi], sb + A_Q + (wm + mi * 16) * 272 + ao);
            const uint32_t bo = (uint32_t)(lane & 7) * 272 + ((lane >> 3) & 1) * 16 + ks * 32;
            #pragma unroll
            for (int ni = 0; ni < 2; ++ni)
                ldm_x2(bF[ni], sb + A_K + (wns + ni * 8) * 272 + bo);
            #pragma unroll
            for (int mi = 0; mi < 4; ++mi)
                #pragma unroll
                for (int ni = 0; ni < 2; ++ni)
                    mma16816h(sacc[mi][ni], aF[mi], bF[ni]);
        }

        // ---- decay + store S (single fp16) ----
        #pragma unroll
        for (int mi = 0; mi < 4; ++mi) {
            #pragma unroll
            for (int ni = 0; ni < 2; ++ni) {
                #pragma unroll
                for (int r = 0; r < 4; ++r) {
                    int il = wm + mi * 16 + erow + (r >> 1) * 8;
                    int jl = wns + ni * 8 + ecol + (r & 1);
                    int dd = (i0 + il) - (j0 + jl);
                    float val = (dd >= 0) ? sacc[mi][ni][r] * sdec[dd] : 0.0f;
                    *(__half*)(smraw + A_S + il * 144 + jl * 2) = __float2half(val);
                }
            }
        }
        __syncthreads();   // S visible; k buffer free

        // prefetch k(jt+1) and vT(jt+1)
        if (jt + 1 < njt) {
            const int jn = (jt + 1) * 64;
            #pragma unroll
            for (int it = 0; it < 4; ++it) {
                int idx = tid + 256 * it;
                int row = idx >> 4, sec = idx & 15;
                size_t g = (rowb + jn + row) * HD + sec * 8;
                uint32_t so = row * 272 + sec * 16;
                cpasync16(sb + A_K + so, g_k16 + g);
            }
            const uint32_t vtn = sb + (cur ? A_VT0 : A_VT1);
            #pragma unroll
            for (int it = 0; it < 4; ++it) {
                int idx = tid + 256 * it;
                int row = idx >> 3, sec = idx & 7;
                size_t g = (colb + row) * SS + n * CC + jn + sec * 8;
                uint32_t so = row * 144 + sec * 16;
                cpasync16(vtn + so, g_vT + g);
            }
            cp_commit();
        }

        // ---- O += S̃ @ v (1-pass) ----
        #pragma unroll
        for (int ks = 0; ks < 4; ++ks) {
            uint32_t aF[4][4], bF[4][2];
            const uint32_t ao = (uint32_t)(lane & 15) * 144 + (lane >> 4) * 16 + ks * 32;
            #pragma unroll
            for (int mi = 0; mi < 4; ++mi)
                ldm_x4(aF[mi], sb + A_S + (wm + mi * 16) * 144 + ao);
            const uint32_t bo = (uint32_t)(lane & 7) * 144 + ((lane >> 3) & 1) * 16 + ks * 32;
            #pragma unroll
            for (int ni = 0; ni < 4; ++ni)
                ldm_x2(bF[ni], vtb + (wno + ni * 8) * 144 + bo);
            #pragma unroll
            for (int mi = 0; mi < 4; ++mi)
                #pragma unroll
                for (int ni = 0; ni < 4; ++ni)
                    mma16816h(oacc[mi][ni], aF[mi], bF[ni]);
        }
    }

    // ---- epilogue: gate-fused fp16 store ----
    #pragma unroll
    for (int mi = 0; mi < 4; ++mi) {
        #pragma unroll
        for (int ni = 0; ni < 4; ++ni) {
            int il = wm + mi * 16 + erow;
            int e  = wno + ni * 8 + ecol;
            size_t o0 = (size_t)(b * SS + n * CC + i0 + il) * HIDN + h * HD + e;
            size_t o1 = o0 + 8 * HIDN;
            float2 g0 = *(const float2*)(g_gate + o0);
            float2 g1 = *(const float2*)(g_gate + o1);
            *(__half2*)(g_ga16 + o0) = __halves2half2(
                __float2half(oacc[mi][ni][0] * g0.x),
                __float2half(oacc[mi][ni][1] * g0.y));
            *(__half2*)(g_ga16 + o1) = __halves2half2(
                __float2half(oacc[mi][ni][2] * g1.x),
                __float2half(oacc[mi][ni][3] * g1.y));
        }
    }
}

// ---------------- launch ----------------
extern "C" void kernel_launch(void* const* d_in, const int* in_sizes, int n_in,
                              void* d_out, int out_size)
{
    const float* x      = (const float*)d_in[0];
    const float* w_qkv  = (const float*)d_in[1];
    const float* w_gate = (const float*)d_in[2];
    const float* w_out  = (const float*)d_in[3];
    const float* slopes = (const float*)d_in[4];
    float* out = (float*)d_out;

    float *qkv_p, *gate_p;
    cudaGetSymbolAddress((void**)&qkv_p,  g_qkv);
    cudaGetSymbolAddress((void**)&gate_p, g_gate);

    __half *x16, *wqh, *wgh, *woh, *ga16;
    cudaGetSymbolAddress((void**)&x16,  g_x16);
    cudaGetSymbolAddress((void**)&wqh,  g_wqkvT_h);
    cudaGetSymbolAddress((void**)&wgh,  g_wgateT_h);
    cudaGetSymbolAddress((void**)&woh,  g_woutT_h);
    cudaGetSymbolAddress((void**)&ga16, g_ga16);

    cudaFuncSetAttribute(mma_gemm_1<EPI_SILU>,
                         cudaFuncAttributeMaxDynamicSharedMemorySize, GEMM1_SMEM);
    cudaFuncSetAttribute(mma_gemm_1<EPI_SIGMOID>,
                         cudaFuncAttributeMaxDynamicSharedMemorySize, GEMM1_SMEM);
    cudaFuncSetAttribute(mma_gemm_1<EPI_NONE>,
                         cudaFuncAttributeMaxDynamicSharedMemorySize, GEMM1_SMEM);
    cudaFuncSetAttribute(attn_mma,
                         cudaFuncAttributeMaxDynamicSharedMemorySize, A_SMEM);
    cudaFuncSetAttribute(kvdelta_mma,
                         cudaFuncAttributeMaxDynamicSharedMemorySize, KD_SMEM);

    // 0) conversions + decay tables
    {
        int n4 = MM * HIDN / 4;
        tohalf_kernel<<<n4 / 256, 256>>>(x, x16, n4);
        dim3 blk(32, 8);
        transp_half_kernel<<<dim3(QKVN / 32, HIDN / 32), blk>>>(w_qkv,  wqh, HIDN, QKVN);
        transp_half_kernel<<<dim3(HIDN / 32, HIDN / 32), blk>>>(w_gate, wgh, HIDN, HIDN);
        transp_half_kernel<<<dim3(HIDN / 32, HIDN / 32), blk>>>(w_out,  woh, HIDN, HIDN);
        dectab_kernel<<<NH, CC>>>(slopes);
    }
    // 1) qkv = silu(x @ w_qkv)
    mma_gemm_1<EPI_SILU><<<dim3(QKVN / 256, MM / 128), 512, GEMM1_SMEM>>>(
        x16, wqh, qkv_p, MM, QKVN);
    // 2) per-head conversions
    splitqkv_norm<<<(BB * SS * NH * 32) / 256, 256>>>();
    {
        dim3 blk(32, 8);
        trans_split_head<<<dim3(SS / 32, HD / 32, BB * NH), blk>>>();
    }
    // 3) gate = sigmoid(x @ w_gate)
    mma_gemm_1<EPI_SIGMOID><<<dim3(HIDN / 256, MM / 128), 512, GEMM1_SMEM>>>(
        x16, wgh, gate_p, MM, HIDN);
    // 4) attention pipeline (fp16 1-pass)
    kvdelta_mma<<<BB * NH * NCC, 256, KD_SMEM>>>();
    scan_kernel<<<BB * NH * 64, 256>>>(slopes);
    {
        dim3 blk(32, 8);
        kvsplitT_kernel<<<dim3(HD / 32, HD / 32, BB * NH * NCC), blk>>>();
    }
    attn_mma<<<dim3(BB * NH * NCC, 2), 256, A_SMEM>>>(slopes);
    // 5) out = (gate*attn) @ w_out
    mma_gemm_1<EPI_NONE><<<dim3(HIDN / 256, MM / 128), 512, GEMM1_SMEM>>>(
        ga16, woh, out, MM, HIDN);
}

// round 12
// speedup vs baseline: 2.3366x; 1.0285x over previous
#include <cuda_runtime.h>
#include <cuda_fp16.h>
#include <math.h>
#include <stdint.h>

// ---------------- problem constants ----------------
#define BB   2
#define SS   4096
#define HIDN 2048
#define NH   16
#define HD   128
#define CC   256
#define NCC  16
#define MM   (BB*SS)          // 8192
#define QKVN (3*HIDN)         // 6144
#define GK   HIDN
#define BKC  64
#define NCHUNK (GK/BKC)       // 32

// ---------------- device scratch ----------------
__device__ float g_kvdelta[(size_t)BB*NH*NCC*HD*HD];
__device__ float g_kvstate[(size_t)BB*NH*NCC*HD*HD];

__device__ __half g_x16[(size_t)MM*HIDN];
__device__ __half g_wqkvT_h[(size_t)QKVN*HIDN];
__device__ __half g_wgateT_h[(size_t)HIDN*HIDN];
__device__ __half g_woutT_h[(size_t)HIDN*HIDN];
__device__ __half g_ga16[(size_t)MM*HIDN];
__device__ __half g_gate16[(size_t)MM*HIDN];

#define PHSZ ((size_t)BB*NH*SS*HD)
__device__ __half g_q16 [PHSZ];                    // [bh][s][d]
__device__ __half g_k16 [PHSZ];                    // [bh][s][d]
__device__ __half g_v16 [PHSZ];                    // [bh][s][d]
__device__ __half g_kdT [PHSZ];                    // [bh][d][s]
__device__ __half g_vT  [PHSZ];                    // [bh][d][s]
__device__ __half g_kvsT[(size_t)BB*NH*NCC*HD*HD]; // [bhn][e][d']
__device__ float g_qdectab[NH*CC], g_kdectab[NH*CC];

// ---------------- epilogues ----------------
#define EPI_SILU    0
#define EPI_SIGMOID 1
#define EPI_NONE    2

__device__ __forceinline__ float apply_epi(float x, int mode) {
    if (mode == EPI_SILU)    return x / (1.0f + expf(-x));
    if (mode == EPI_SIGMOID) return 1.0f / (1.0f + expf(-x));
    return x;
}

// ---------------- base-ISA tensor-core helpers ----------------
__device__ __forceinline__ uint32_t smem_u32(const void* p) {
    uint32_t a;
    asm("{ .reg .u64 t; cvta.to.shared.u64 t, %1; cvt.u32.u64 %0, t; }" : "=r"(a) : "l"(p));
    return a;
}
__device__ __forceinline__ void cpasync16(uint32_t saddr, const void* g) {
    asm volatile("cp.async.cg.shared.global [%0], [%1], 16;" :: "r"(saddr), "l"(g));
}
__device__ __forceinline__ void cp_commit() {
    asm volatile("cp.async.commit_group;" ::: "memory");
}
template<int N> __device__ __forceinline__ void cp_wait() {
    asm volatile("cp.async.wait_group %0;" :: "n"(N) : "memory");
}
__device__ __forceinline__ void ldm_x4(uint32_t* r, uint32_t addr) {
    asm volatile("ldmatrix.sync.aligned.m8n8.x4.shared.b16 {%0,%1,%2,%3}, [%4];"
                 : "=r"(r[0]), "=r"(r[1]), "=r"(r[2]), "=r"(r[3]) : "r"(addr));
}
__device__ __forceinline__ void ldm_x2(uint32_t* r, uint32_t addr) {
    asm volatile("ldmatrix.sync.aligned.m8n8.x2.shared.b16 {%0,%1}, [%2];"
                 : "=r"(r[0]), "=r"(r[1]) : "r"(addr));
}
__device__ __forceinline__ void mma16816h(float* c, const uint32_t* a, const uint32_t* b) {
    asm volatile(
        "mma.sync.aligned.m16n8k16.row.col.f32.f16.f16.f32 "
        "{%0,%1,%2,%3},{%4,%5,%6,%7},{%8,%9},{%0,%1,%2,%3};"
        : "+f"(c[0]), "+f"(c[1]), "+f"(c[2]), "+f"(c[3])
        : "r"(a[0]), "r"(a[1]), "r"(a[2]), "r"(a[3]), "r"(b[0]), "r"(b[1]));
}

#define LDSW   144

// ---------------- fp16 1-pass GEMM core (tile 128x256, 512 thr) ----------------
#define HA_SZ  (128 * LDSW)               // 18432
#define HB_SZ  (256 * LDSW)               // 36864
#define H1BUF  (HA_SZ + HB_SZ)            // 55296
#define GEMM1_SMEM (2 * H1BUF)            // 110592

// EPIMODE: 0 silu->qkv split store, 1 sigmoid->half gate, 2 none->float out
template<int EPIMODE>
__global__ __launch_bounds__(512) void mma_gemm_1(
    const __half* __restrict__ A, const __half* __restrict__ Bh,
    float* __restrict__ Cf, int M, int N)
{
    extern __shared__ char smraw[];
    const uint32_t sb = smem_u32(smraw);

    const int tid  = threadIdx.x;
    const int lane = tid & 31;
    const int wid  = tid >> 5;
    const int bm = blockIdx.y * 128;
    const int bn = blockIdx.x * 256;
    const int wm = (wid >> 3) * 64;
    const int wn = (wid & 7) * 32;

    auto prefetch = [&](int c, int buf) {
        const uint32_t bbase = sb + buf * H1BUF;
        const int k0 = c * BKC;
        #pragma unroll
        for (int i = 0; i < 2; ++i) {
            int idx = tid + 512 * i;
            int row = idx >> 3, sec = idx & 7;
            const uint32_t so = row * LDSW + sec * 16;
            const size_t ga = (size_t)(bm + row) * GK + k0 + sec * 8;
            cpasync16(bbase + so, A + ga);
        }
        #pragma unroll
        for (int i = 0; i < 4; ++i) {
            int idx = tid + 512 * i;
            int row = idx >> 3, sec = idx & 7;
            const uint32_t so = row * LDSW + sec * 16;
            const size_t gb = (size_t)(bn + row) * GK + k0 + sec * 8;
            cpasync16(bbase + HA_SZ + so, Bh + gb);
        }
        cp_commit();
    };

    float acc[4][4][4];
    #pragma unroll
    for (int mi = 0; mi < 4; ++mi)
        #pragma unroll
        for (int ni = 0; ni < 4; ++ni)
            #pragma unroll
            for (int r = 0; r < 4; ++r) acc[mi][ni][r] = 0.0f;

    const uint32_t aOff = (uint32_t)(wm + (lane & 15)) * LDSW + (lane >> 4) * 16;
    const uint32_t bOff = (uint32_t)(wn + (lane & 7))  * LDSW + ((lane >> 3) & 1) * 16;

    prefetch(0, 0);

    for (int c = 0; c < NCHUNK; ++c) {
        const int cur = c & 1;
        if (c + 1 < NCHUNK) prefetch(c + 1, cur ^ 1);
        if (c + 1 < NCHUNK) cp_wait<1>(); else cp_wait<0>();
        __syncthreads();

        const uint32_t bbase = sb + cur * H1BUF;
        #pragma unroll
        for (int ks = 0; ks < 4; ++ks) {
            const uint32_t kso = ks * 32;
            uint32_t aF[4][4], bF[4][2];
            #pragma unroll
            for (int mi = 0; mi < 4; ++mi)
                ldm_x4(aF[mi], bbase + aOff + mi * 16 * LDSW + kso);
            #pragma unroll
            for (int ni = 0; ni < 4; ++ni)
                ldm_x2(bF[ni], bbase + HA_SZ + bOff + ni * 8 * LDSW + kso);
            #pragma unroll
            for (int mi = 0; mi < 4; ++mi)
                #pragma unroll
                for (int ni = 0; ni < 4; ++ni)
                    mma16816h(acc[mi][ni], aF[mi], bF[ni]);
        }
        __syncthreads();
    }

    const int erow = lane >> 2;
    const int ecol = 2 * (lane & 3);
    #pragma unroll
    for (int mi = 0; mi < 4; ++mi) {
        #pragma unroll
        for (int ni = 0; ni < 4; ++ni) {
            const int gr0 = bm + wm + mi * 16 + erow;
            const int gc  = bn + wn + ni * 8 + ecol;
            float v0 = apply_epi(acc[mi][ni][0], (EPIMODE == 0) ? EPI_SILU :
                                 (EPIMODE == 1) ? EPI_SIGMOID : EPI_NONE);
            float v1 = apply_epi(acc[mi][ni][1], (EPIMODE == 0) ? EPI_SILU :
                                 (EPIMODE == 1) ? EPI_SIGMOID : EPI_NONE);
            float v2 = apply_epi(acc[mi][ni][2], (EPIMODE == 0) ? EPI_SILU :
                                 (EPIMODE == 1) ? EPI_SIGMOID : EPI_NONE);
            float v3 = apply_epi(acc[mi][ni][3], (EPIMODE == 0) ? EPI_SILU :
                                 (EPIMODE == 1) ? EPI_SIGMOID : EPI_NONE);
            if (EPIMODE == 0) {
                // qkv: decode col -> (tensor, head, d); store fp16 per-head [bh][s][d]
                const int tensor = gc >> 11;
                const int rem = gc & 2047;
                const int h = rem >> 7;
                const int d = rem & 127;
                __half* dst = (tensor == 0) ? g_q16 : (tensor == 1) ? g_k16 : g_v16;
                const int b0 = gr0 >> 12, s0v = gr0 & 4095;
                const int r1 = gr0 + 8;
                const int b1 = r1 >> 12, s1v = r1 & 4095;
                size_t o0 = ((size_t)(b0 * NH + h) * SS + s0v) * HD + d;
                size_t o1 = ((size_t)(b1 * NH + h) * SS + s1v) * HD + d;
                *(__half2*)(dst + o0) = __halves2half2(__float2half(v0), __float2half(v1));
                *(__half2*)(dst + o1) = __halves2half2(__float2half(v2), __float2half(v3));
            } else if (EPIMODE == 1) {
                size_t o0 = (size_t)gr0 * N + gc;
                *(__half2*)(g_gate16 + o0)           = __halves2half2(__float2half(v0), __float2half(v1));
                *(__half2*)(g_gate16 + o0 + 8 * (size_t)N) = __halves2half2(__float2half(v2), __float2half(v3));
            } else {
                *(float2*)(Cf + (size_t)gr0 * N + gc)       = make_float2(v0, v1);
                *(float2*)(Cf + (size_t)(gr0 + 8) * N + gc) = make_float2(v2, v3);
            }
        }
    }
}

// ---------------- conversion kernels ----------------
__device__ __forceinline__ void store4h(__half* d, size_t o, float4 v)
{
    *(__half2*)(d + o)     = __halves2half2(__float2half(v.x), __float2half(v.y));
    *(__half2*)(d + o + 2) = __halves2half2(__float2half(v.z), __float2half(v.w));
}

__global__ __launch_bounds__(256) void tohalf_kernel(
    const float* __restrict__ in, __half* __restrict__ d16, int n4)
{
    int i = blockIdx.x * 256 + threadIdx.x;
    if (i >= n4) return;
    store4h(d16, (size_t)i * 4, ((const float4*)in)[i]);
}

__global__ void transp_half_kernel(
    const float* __restrict__ w, __half* __restrict__ t, int K, int N)
{
    __shared__ float ts[32][33];
    const int n0 = blockIdx.x * 32, k0 = blockIdx.y * 32;
    const int x = threadIdx.x, y = threadIdx.y;
    #pragma unroll
    for (int r = 0; r < 32; r += 8)
        ts[y + r][x] = w[(size_t)(k0 + y + r) * N + n0 + x];
    __syncthreads();
    #pragma unroll
    for (int r = 0; r < 32; r += 8) {
        size_t o = (size_t)(n0 + y + r) * K + k0 + x;
        t[o] = __float2half(ts[x][y + r]);
    }
}

__global__ void dectab_kernel(const float* __restrict__ slopes)
{
    int h = blockIdx.x, i = threadIdx.x;
    float s = slopes[h];
    g_qdectab[h * CC + i] = expf(-s * (float)(i + 1));
    g_kdectab[h * CC + i] = expf(-s * (float)(CC - 1 - i));
}

// k16,v16 [bh][s][d] -> kdT (with decay), vT [bh][d][s]  (fp16 in/out)
__global__ void trans_split_head()
{
    __shared__ float tk[32][33], tv[32][33];
    const int z  = blockIdx.z;
    const int h  = z & 15;
    const int s0 = blockIdx.x * 32;
    const int d0 = blockIdx.y * 32;
    const int x = threadIdx.x, y = threadIdx.y;

    #pragma unroll
    for (int r = 0; r < 32; r += 8) {
        size_t base = ((size_t)z * SS + s0 + y + r) * HD + d0 + x;
        tk[y + r][x] = __half2float(g_k16[base]);
        tv[y + r][x] = __half2float(g_v16[base]);
    }
    __syncthreads();
    #pragma unroll
    for (int r = 0; r < 32; r += 8) {
        int d = d0 + y + r;
        int s = s0 + x;
        float kdec = g_kdectab[h * CC + (s & (CC - 1))];
        size_t o = ((size_t)z * HD + d) * SS + s;
        g_kdT[o] = __float2half(tk[x][y + r] * kdec);
        g_vT[o]  = __float2half(tv[x][y + r]);
    }
}

// g_kvstate [bhn][d'][e] -> kvsT [bhn][e][d'] fp16
__global__ void kvsplitT_kernel()
{
    __shared__ float t[32][33];
    const int bhn = blockIdx.z;
    const int d0 = blockIdx.x * 32;
    const int e0 = blockIdx.y * 32;
    const int x = threadIdx.x, y = threadIdx.y;
    const size_t base = (size_t)bhn * HD * HD;

    #pragma unroll
    for (int r = 0; r < 32; r += 8)
        t[y + r][x] = g_kvstate[base + (size_t)(d0 + y + r) * HD + e0 + x];
    __syncthreads();
    #pragma unroll
    for (int r = 0; r < 32; r += 8) {
        size_t o = base + (size_t)(e0 + y + r) * HD + d0 + x;
        g_kvsT[o] = __float2half(t[x][y + r]);
    }
}

// ---------------- kvdelta via HMMA (fp16 1-pass, double-buffered) ----------------
#define KD_MAT  18432
#define KD_BUF  (2 * KD_MAT)          // 36864
#define KD_SMEM (2 * KD_BUF)          // 73728

__global__ __launch_bounds__(256) void kvdelta_mma()
{
    extern __shared__ char smraw[];
    const uint32_t sb = smem_u32(smraw);

    const int blk = blockIdx.x;
    const int n  = blk & (NCC - 1);
    const int bh = blk >> 4;
    const size_t colb = (size_t)bh * HD;

    const int tid = threadIdx.x, lane = tid & 31, wid = tid >> 5;
    const int wm = (wid >> 2) * 64;
    const int wn = (wid & 3) * 32;

    auto prefetch = [&](int kt, int buf) {
        const uint32_t bbase = sb + buf * KD_BUF;
        const int k0 = n * CC + kt * 64;
        #pragma unroll
        for (int it = 0; it < 4; ++it) {
            int idx = tid + 256 * it;
            int row = idx >> 3, sec = idx & 7;
            size_t g = (colb + row) * SS + k0 + sec * 8;
            uint32_t so = row * 144 + sec * 16;
            cpasync16(bbase + 0 * KD_MAT + so, g_kdT + g);
            cpasync16(bbase + 1 * KD_MAT + so, g_vT + g);
        }
        cp_commit();
    };

    float acc[4][4][4];
    #pragma unroll
    for (int mi = 0; mi < 4; ++mi)
        #pragma unroll
        for (int ni = 0; ni < 4; ++ni)
            #pragma unroll
            for (int r = 0; r < 4; ++r) acc[mi][ni][r] = 0.0f;

    prefetch(0, 0);

    for (int kt = 0; kt < 4; ++kt) {
        const int cur = kt & 1;
        if (kt + 1 < 4) prefetch(kt + 1, cur ^ 1);
        if (kt + 1 < 4) cp_wait<1>(); else cp_wait<0>();
        __syncthreads();

        const uint32_t bbase = sb + cur * KD_BUF;
        #pragma unroll
        for (int ks = 0; ks < 4; ++ks) {
            uint32_t aF[4][4], bF[4][2];
            const uint32_t ao = (uint32_t)(lane & 15) * 144 + (lane >> 4) * 16 + ks * 32;
            #pragma unroll
            for (int mi = 0; mi < 4; ++mi)
                ldm_x4(aF[mi], bbase + 0 * KD_MAT + (wm + mi * 16) * 144 + ao);
            const uint32_t bo = (uint32_t)(lane & 7) * 144 + ((lane >> 3) & 1) * 16 + ks * 32;
            #pragma unroll
            for (int ni = 0; ni < 4; ++ni)
                ldm_x2(bF[ni], bbase + 1 * KD_MAT + (wn + ni * 8) * 144 + bo);
            #pragma unroll
            for (int mi = 0; mi < 4; ++mi)
                #pragma unroll
                for (int ni = 0; ni < 4; ++ni)
                    mma16816h(acc[mi][ni], aF[mi], bF[ni]);
        }
        __syncthreads();
    }

    const int erow = lane >> 2, ecol = 2 * (lane & 3);
    float* out = &g_kvdelta[(size_t)blk * HD * HD];
    #pragma unroll
    for (int mi = 0; mi < 4; ++mi) {
        #pragma unroll
        for (int ni = 0; ni < 4; ++ni) {
            int d = wm + mi * 16 + erow;
            int e = wn + ni * 8 + ecol;
            *(float2*)(out + (size_t)d * HD + e)       = make_float2(acc[mi][ni][0], acc[mi][ni][1]);
            *(float2*)(out + (size_t)(d + 8) * HD + e) = make_float2(acc[mi][ni][2], acc[mi][ni][3]);
        }
    }
}

// ---------------- scan (parallel) ----------------
__global__ __launch_bounds__(256) void scan_kernel(const float* __restrict__ slopes)
{
    const int gid = blockIdx.x * 256 + threadIdx.x;
    const int bh  = gid >> 14;
    const int p   = gid & 16383;
    const float bd = expf(-slopes[bh & (NH - 1)] * (float)CC);
    const size_t base = (size_t)bh * NCC * HD * HD + p;

    float st = 0.0f;
    #pragma unroll
    for (int nn = 0; nn < NCC; nn++) {
        g_kvstate[base + (size_t)nn * HD * HD] = st;
        st = bd * st + g_kvdelta[base + (size_t)nn * HD * HD];
    }
}

// ---------------- fused attention via HMMA (fp16 1-pass, pipelined, inter-first) ----------------
#define A_Q     0
#define A_K     34816
#define A_VT0   52224
#define A_VT1   70656
#define A_S     89088
#define A_SMEM  107520
#define A_KVS   70656

__global__ __launch_bounds__(256) void attn_mma(const float* __restrict__ slopes)
{
    extern __shared__ char smraw[];
    const uint32_t sb = smem_u32(smraw);
    __shared__ float sdec[CC];

    const int blk = blockIdx.x;
    const int itile = blockIdx.y;
    const int n  = blk & (NCC - 1);
    const int bh = blk >> 4;
    const int h  = bh & (NH - 1);
    const int b  = bh >> 4;
    const float s = slopes[h];

    const int tid = threadIdx.x, lane = tid & 31, wid = tid >> 5;
    sdec[tid] = expf(-s * (float)tid);
    const float fexp = expf(-s);

    const size_t rowb = (size_t)bh * SS + n * CC;
    const size_t colb = (size_t)bh * HD;
    const int i0 = itile * 128;

    // group 0: q + kvsT
    #pragma unroll
    for (int it = 0; it < 8; ++it) {
        int idx = tid + 256 * it;
        int row = idx >> 4, sec = idx & 15;
        size_t g = (rowb + i0 + row) * HD + sec * 8;
        uint32_t so = row * 272 + sec * 16;
        cpasync16(sb + A_Q + so, g_q16 + g);
    }
    {
        const size_t kvb = (size_t)blk * HD * HD;
        #pragma unroll
        for (int it = 0; it < 8; ++it) {
            int idx = tid + 256 * it;
            int row = idx >> 4, sec = idx & 15;
            size_t g = kvb + (size_t)row * HD + sec * 8;
            uint32_t so = row * 272 + sec * 16;
            cpasync16(sb + A_KVS + so, g_kvsT + g);
        }
    }
    cp_commit();

    // group 1: vT(j=0) into buf0
    #pragma unroll
    for (int it = 0; it < 4; ++it) {
        int idx = tid + 256 * it;
        int row = idx >> 3, sec = idx & 7;
        size_t g = (colb + row) * SS + n * CC + sec * 8;
        uint32_t so = row * 144 + sec * 16;
        cpasync16(sb + A_VT0 + so, g_vT + g);
    }
    cp_commit();

    const int wm  = (wid >> 2) * 64;
    const int wns = (wid & 3) * 16;
    const int wno = (wid & 3) * 32;
    const int erow = lane >> 2, ecol = 2 * (lane & 3);

    float oacc[4][4][4];
    #pragma unroll
    for (int mi = 0; mi < 4; ++mi)
        #pragma unroll
        for (int ni = 0; ni < 4; ++ni)
            #pragma unroll
            for (int r = 0; r < 4; ++r) oacc[mi][ni][r] = 0.0f;

    // ---- inter FIRST: oacc = q @ kvsT, then row-scale by qdec ----
    cp_wait<1>();
    __syncthreads();

    #pragma unroll
    for (int ks = 0; ks < 8; ++ks) {
        uint32_t aF[4][4], bF[4][2];
        const uint32_t ao = (uint32_t)(lane & 15) * 272 + (lane >> 4) * 16 + ks * 32;
        #pragma unroll
        for (int mi = 0; mi < 4; ++mi)
            ldm_x4(aF[mi], sb + A_Q + (wm + mi * 16) * 272 + ao);
        const uint32_t bo = (uint32_t)(lane & 7) * 272 + ((lane >> 3) & 1) * 16 + ks * 32;
        #pragma unroll
        for (int ni = 0; ni < 4; ++ni)
            ldm_x2(bF[ni], sb + A_KVS + (wno + ni * 8) * 272 + bo);
        #pragma unroll
        for (int mi = 0; mi < 4; ++mi)
            #pragma unroll
            for (int ni = 0; ni < 4; ++ni)
                mma16816h(oacc[mi][ni], aF[mi], bF[ni]);
    }
    #pragma unroll
    for (int mi = 0; mi < 4; ++mi) {
        const int il0 = wm + mi * 16 + erow;
        const float qd0 = sdec[i0 + il0] * fexp;
        const float qd1 = sdec[i0 + il0 + 8] * fexp;
        #pragma unroll
        for (int ni = 0; ni < 4; ++ni) {
            oacc[mi][ni][0] *= qd0;
            oacc[mi][ni][1] *= qd0;
            oacc[mi][ni][2] *= qd1;
            oacc[mi][ni][3] *= qd1;
        }
    }
    __syncthreads();

    // load k(0)
    #pragma unroll
    for (int it = 0; it < 4; ++it) {
        int idx = tid + 256 * it;
        int row = idx >> 4, sec = idx & 15;
        size_t g = (rowb + row) * HD + sec * 8;
        uint32_t so = row * 272 + sec * 16;
        cpasync16(sb + A_K + so, g_k16 + g);
    }
    cp_commit();

    const int njt = 2 * (itile + 1);
    for (int jt = 0; jt < njt; ++jt) {
        const int j0 = jt * 64;
        const int cur = jt & 1;
        const uint32_t vtb = sb + (cur ? A_VT1 : A_VT0);

        cp_wait<0>();
        __syncthreads();

        // ---- S = q @ k^T ----
        float sacc[4][2][4];
        #pragma unroll
        for (int mi = 0; mi < 4; ++mi)
            #pragma unroll
            for (int ni = 0; ni < 2; ++ni)
                #pragma unroll
                for (int r = 0; r < 4; ++r) sacc[mi][ni][r] = 0.0f;

        #pragma unroll
        for (int ks = 0; ks < 8; ++ks) {
            uint32_t aF[4][4], bF[2][2];
            const uint32_t ao = (uint32_t)(lane & 15) * 272 + (lane >> 4) * 16 + ks * 32;
            #pragma unroll
            for (int mi = 0; mi < 4; ++mi)
                ldm_x4(aF[mi], sb + A_Q + (wm + mi * 16) * 272 + ao);
            const uint32_t bo = (uint32_t)(lane & 7) * 272 + ((lane >> 3) & 1) * 16 + ks * 32;
            #pragma unroll
            for (int ni = 0; ni < 2; ++ni)
                ldm_x2(bF[ni], sb + A_K + (wns + ni * 8) * 272 + bo);
            #pragma unroll
            for (int mi = 0; mi < 4; ++mi)
                #pragma unroll
                for (int ni = 0; ni < 2; ++ni)
                    mma16816h(sacc[mi][ni], aF[mi], bF[ni]);
        }

        // ---- decay + store S ----
        #pragma unroll
        for (int mi = 0; mi < 4; ++mi) {
            #pragma unroll
            for (int ni = 0; ni < 2; ++ni) {
                #pragma unroll
                for (int r = 0; r < 4; ++r) {
                    int il = wm + mi * 16 + erow + (r >> 1) * 8;
                    int jl = wns + ni * 8 + ecol + (r & 1);
                    int dd = (i0 + il) - (j0 + jl);
                    float val = (dd >= 0) ? sacc[mi][ni][r] * sdec[dd] : 0.0f;
                    *(__half*)(smraw + A_S + il * 144 + jl * 2) = __float2half(val);
                }
            }
        }
        __syncthreads();

        // prefetch k(jt+1) and vT(jt+1)
        if (jt + 1 < njt) {
            const int jn = (jt + 1) * 64;
            #pragma unroll
            for (int it = 0; it < 4; ++it) {
                int idx = tid + 256 * it;
                int row = idx >> 4, sec = idx & 15;
                size_t g = (rowb + jn + row) * HD + sec * 8;
                uint32_t so = row * 272 + sec * 16;
                cpasync16(sb + A_K + so, g_k16 + g);
            }
            const uint32_t vtn = sb + (cur ? A_VT0 : A_VT1);
            #pragma unroll
            for (int it = 0; it < 4; ++it) {
                int idx = tid + 256 * it;
                int row = idx >> 3, sec = idx & 7;
                size_t g = (colb + row) * SS + n * CC + jn + sec * 8;
                uint32_t so = row * 144 + sec * 16;
                cpasync16(vtn + so, g_vT + g);
            }
            cp_commit();
        }

        // ---- O += S̃ @ v ----
        #pragma unroll
        for (int ks = 0; ks < 4; ++ks) {
            uint32_t aF[4][4], bF[4][2];
            const uint32_t ao = (uint32_t)(lane & 15) * 144 + (lane >> 4) * 16 + ks * 32;
            #pragma unroll
            for (int mi = 0; mi < 4; ++mi)
                ldm_x4(aF[mi], sb + A_S + (wm + mi * 16) * 144 + ao);
            const uint32_t bo = (uint32_t)(lane & 7) * 144 + ((lane >> 3) & 1) * 16 + ks * 32;
            #pragma unroll
            for (int ni = 0; ni < 4; ++ni)
                ldm_x2(bF[ni], vtb + (wno + ni * 8) * 144 + bo);
            #pragma unroll
            for (int mi = 0; mi < 4; ++mi)
                #pragma unroll
                for (int ni = 0; ni < 4; ++ni)
                    mma16816h(oacc[mi][ni], aF[mi], bF[ni]);
        }
    }

    // ---- epilogue: gate-fused fp16 store ----
    #pragma unroll
    for (int mi = 0; mi < 4; ++mi) {
        #pragma unroll
        for (int ni = 0; ni < 4; ++ni) {
            int il = wm + mi * 16 + erow;
            int e  = wno + ni * 8 + ecol;
            size_t o0 = (size_t)(b * SS + n * CC + i0 + il) * HIDN + h * HD + e;
            size_t o1 = o0 + 8 * HIDN;
            float2 g0 = __half22float2(*(const __half2*)(g_gate16 + o0));
            float2 g1 = __half22float2(*(const __half2*)(g_gate16 + o1));
            *(__half2*)(g_ga16 + o0) = __halves2half2(
                __float2half(oacc[mi][ni][0] * g0.x),
                __float2half(oacc[mi][ni][1] * g0.y));
            *(__half2*)(g_ga16 + o1) = __halves2half2(
                __float2half(oacc[mi][ni][2] * g1.x),
                __float2half(oacc[mi][ni][3] * g1.y));
        }
    }
}

// ---------------- launch ----------------
extern "C" void kernel_launch(void* const* d_in, const int* in_sizes, int n_in,
                              void* d_out, int out_size)
{
    const float* x      = (const float*)d_in[0];
    const float* w_qkv  = (const float*)d_in[1];
    const float* w_gate = (const float*)d_in[2];
    const float* w_out  = (const float*)d_in[3];
    const float* slopes = (const float*)d_in[4];
    float* out = (float*)d_out;

    __half *x16, *wqh, *wgh, *woh, *ga16;
    cudaGetSymbolAddress((void**)&x16,  g_x16);
    cudaGetSymbolAddress((void**)&wqh,  g_wqkvT_h);
    cudaGetSymbolAddress((void**)&wgh,  g_wgateT_h);
    cudaGetSymbolAddress((void**)&woh,  g_woutT_h);
    cudaGetSymbolAddress((void**)&ga16, g_ga16);

    cudaFuncSetAttribute(mma_gemm_1<0>,
                         cudaFuncAttributeMaxDynamicSharedMemorySize, GEMM1_SMEM);
    cudaFuncSetAttribute(mma_gemm_1<1>,
                         cudaFuncAttributeMaxDynamicSharedMemorySize, GEMM1_SMEM);
    cudaFuncSetAttribute(mma_gemm_1<2>,
                         cudaFuncAttributeMaxDynamicSharedMemorySize, GEMM1_SMEM);
    cudaFuncSetAttribute(attn_mma,
                         cudaFuncAttributeMaxDynamicSharedMemorySize, A_SMEM);
    cudaFuncSetAttribute(kvdelta_mma,
                         cudaFuncAttributeMaxDynamicSharedMemorySize, KD_SMEM);

    // 0) conversions + decay tables
    {
        int n4 = MM * HIDN / 4;
        tohalf_kernel<<<n4 / 256, 256>>>(x, x16, n4);
        dim3 blk(32, 8);
        transp_half_kernel<<<dim3(QKVN / 32, HIDN / 32), blk>>>(w_qkv,  wqh, HIDN, QKVN);
        transp_half_kernel<<<dim3(HIDN / 32, HIDN / 32), blk>>>(w_gate, wgh, HIDN, HIDN);
        transp_half_kernel<<<dim3(HIDN / 32, HIDN / 32), blk>>>(w_out,  woh, HIDN, HIDN);
        dectab_kernel<<<NH, CC>>>(slopes);
    }
    // 1) qkv = silu(x @ w_qkv) -> q16/k16/v16 directly (per-head fp16)
    mma_gemm_1<0><<<dim3(QKVN / 256, MM / 128), 512, GEMM1_SMEM>>>(
        x16, wqh, nullptr, MM, QKVN);
    // 2) kdT / vT transposes (fp16 sources)
    {
        dim3 blk(32, 8);
        trans_split_head<<<dim3(SS / 32, HD / 32, BB * NH), blk>>>();
    }
    // 3) gate = sigmoid(x @ w_gate) -> fp16
    mma_gemm_1<1><<<dim3(HIDN / 256, MM / 128), 512, GEMM1_SMEM>>>(
        x16, wgh, nullptr, MM, HIDN);
    // 4) attention pipeline
    kvdelta_mma<<<BB * NH * NCC, 256, KD_SMEM>>>();
    scan_kernel<<<BB * NH * 64, 256>>>(slopes);
    {
        dim3 blk(32, 8);
        kvsplitT_kernel<<<dim3(HD / 32, HD / 32, BB * NH * NCC), blk>>>();
    }
    attn_mma<<<dim3(BB * NH * NCC, 2), 256, A_SMEM>>>(slopes);
    // 5) out = (gate*attn) @ w_out
    mma_gemm_1<2><<<dim3(HIDN / 256, MM / 128), 512, GEMM1_SMEM>>>(
        ga16, woh, out, MM, HIDN);
}